// round 12
// baseline (speedup 1.0000x reference)
#include <cuda_runtime.h>
#include <cuda_bf16.h>
#include <stdint.h>

#define BATCH 4096
#define SEQT  256
#define DIN0  128
#define HID   64
#define G3    192
#define MTOT  (BATCH * SEQT)   // 1048576 rows

// Scratch (static: no allocations allowed)
__device__ float g_gx[(long)MTOT * G3];   // fp32 layer-1 gate preactivations incl b_ih0

typedef unsigned long long u64;
typedef unsigned int u32;

// ---------------------------------------------------------------- common
__device__ __forceinline__ void mma16816(float* c, const u32* a, const u32* b) {
    asm volatile(
        "mma.sync.aligned.m16n8k16.row.col.f32.bf16.bf16.f32 "
        "{%0,%1,%2,%3}, {%4,%5,%6,%7}, {%8,%9}, {%0,%1,%2,%3};"
        : "+f"(c[0]), "+f"(c[1]), "+f"(c[2]), "+f"(c[3])
        : "r"(a[0]), "r"(a[1]), "r"(a[2]), "r"(a[3]), "r"(b[0]), "r"(b[1]));
}
__device__ __forceinline__ u32 packhi(float a, float b) {
    return ((u32)__bfloat16_as_ushort(__float2bfloat16(a)))
         | ((u32)__bfloat16_as_ushort(__float2bfloat16(b)) << 16);
}
__device__ __forceinline__ u32 packlo(float a, float b) {
    float al = a - __bfloat162float(__float2bfloat16(a));
    float bl = b - __bfloat162float(__float2bfloat16(b));
    return ((u32)__bfloat16_as_ushort(__float2bfloat16(al)))
         | ((u32)__bfloat16_as_ushort(__float2bfloat16(bl)) << 16);
}
__device__ __forceinline__ float tanha(float x) {
    float y;
    asm("tanh.approx.f32 %0, %1;" : "=f"(y) : "f"(x));
    return y;
}
__device__ __forceinline__ float siga(float x) {
    return fmaf(0.5f, tanha(0.5f * x), 0.5f);
}
// 3-term split-bf16 MMA: w = {hi(k0,k0+1), hi(k0+8,k0+9), lo(k0,k0+1), lo(k0+8,k0+9)}
__device__ __forceinline__ void mma3(float* acc, const u32* ah, const u32* al, uint4 w) {
    u32 wh[2] = {w.x, w.y};
    u32 wl[2] = {w.z, w.w};
    mma16816(acc, ah, wh);
    mma16816(acc, ah, wl);
    mma16816(acc, al, wh);
}

// ================================================================= GEMM1
// gx1[m][n] = x[m]·Wih0[n] + bih0[n]  (R8 verbatim — proven)
template<int K>
__global__ __launch_bounds__(256, 1)
void proj_gemm(const float* __restrict__ X,
               const float* __restrict__ W,
               const float* __restrict__ bias,
               float* __restrict__ OUT)
{
    constexpr int P      = K + 8;
    constexpr int NTILES = MTOT / 64;
    constexpr int ABUF   = 64 * P * 2;
    constexpr int BBUF   = G3 * P * 2;
    constexpr int NPF    = K / 16;

    extern __shared__ char smem[];
    char* Bh    = smem;
    char* Bl    = Bh + BBUF;
    char* Abase = Bl + BBUF;

    const int tid = threadIdx.x;
    const int wid = tid >> 5;
    const int lid = tid & 31;
    const int g   = lid >> 2;
    const int cp  = lid & 3;
    const int GRID = gridDim.x;

    for (int c = tid; c < G3 * (K / 8); c += 256) {
        int row = c / (K / 8), k = (c % (K / 8)) * 8;
        const float4* src = (const float4*)(W + row * K + k);
        float4 v0 = src[0], v1 = src[1];
        int byte = (row * P + k) * 2;
        *(uint4*)(Bh + byte) = make_uint4(packhi(v0.x, v0.y), packhi(v0.z, v0.w),
                                          packhi(v1.x, v1.y), packhi(v1.z, v1.w));
        *(uint4*)(Bl + byte) = make_uint4(packlo(v0.x, v0.y), packlo(v0.z, v0.w),
                                          packlo(v1.x, v1.y), packlo(v1.z, v1.w));
    }

    const int mrow = (wid & 1) * 32;
    const int ncol = (wid >> 1) * 48;

    float breg[6][2];
#pragma unroll
    for (int nt = 0; nt < 6; nt++) {
        int col = ncol + nt * 8 + 2 * cp;
        breg[nt][0] = bias[col];
        breg[nt][1] = bias[col + 1];
    }

    float4 pfA[NPF];
    long tile0 = blockIdx.x;
    if (tile0 < NTILES) {
#pragma unroll
        for (int q = 0; q < NPF; q++) {
            int idx = tid + 256 * q;
            int row = idx / (K / 4), k = (idx % (K / 4)) * 4;
            pfA[q] = *(const float4*)(X + (tile0 * 64 + row) * K + k);
        }
        char* Ah = Abase;
        char* Al = Abase + ABUF;
#pragma unroll
        for (int q = 0; q < NPF; q++) {
            int idx = tid + 256 * q;
            int row = idx / (K / 4), k = (idx % (K / 4)) * 4;
            float4 v = pfA[q];
            int byte = (row * P + k) * 2;
            *(uint2*)(Ah + byte) = make_uint2(packhi(v.x, v.y), packhi(v.z, v.w));
            *(uint2*)(Al + byte) = make_uint2(packlo(v.x, v.y), packlo(v.z, v.w));
        }
    }
    __syncthreads();

    int it = 0;
    for (long tile = tile0; tile < NTILES; tile += GRID, it++) {
        const long nxt = tile + GRID;
        if (nxt < NTILES) {
#pragma unroll
            for (int q = 0; q < NPF; q++) {
                int idx = tid + 256 * q;
                int row = idx / (K / 4), k = (idx % (K / 4)) * 4;
                pfA[q] = *(const float4*)(X + (nxt * 64 + row) * K + k);
            }
        }

        char* Ah = Abase + (it & 1) * 2 * ABUF;
        char* Al = Ah + ABUF;

        float acc[2][6][4];
#pragma unroll
        for (int mt = 0; mt < 2; mt++)
#pragma unroll
            for (int nt = 0; nt < 6; nt++)
#pragma unroll
                for (int q = 0; q < 4; q++) acc[mt][nt][q] = 0.0f;

#pragma unroll
        for (int ks = 0; ks < K / 16; ks++) {
            const int kb = ks * 16;
            u32 ahf[2][4], alf[2][4];
#pragma unroll
            for (int mt = 0; mt < 2; mt++) {
                int r = mrow + mt * 16 + g;
                int c0b = (r * P + kb + 2 * cp) * 2;
                int c1b = ((r + 8) * P + kb + 2 * cp) * 2;
                ahf[mt][0] = *(const u32*)(Ah + c0b);
                ahf[mt][1] = *(const u32*)(Ah + c1b);
                ahf[mt][2] = *(const u32*)(Ah + c0b + 16);
                ahf[mt][3] = *(const u32*)(Ah + c1b + 16);
                alf[mt][0] = *(const u32*)(Al + c0b);
                alf[mt][1] = *(const u32*)(Al + c1b);
                alf[mt][2] = *(const u32*)(Al + c0b + 16);
                alf[mt][3] = *(const u32*)(Al + c1b + 16);
            }
            u32 bhf[6][2], blf[6][2];
#pragma unroll
            for (int nt = 0; nt < 6; nt++) {
                int n = ncol + nt * 8 + g;
                int bb = (n * P + kb + 2 * cp) * 2;
                bhf[nt][0] = *(const u32*)(Bh + bb);
                bhf[nt][1] = *(const u32*)(Bh + bb + 16);
                blf[nt][0] = *(const u32*)(Bl + bb);
                blf[nt][1] = *(const u32*)(Bl + bb + 16);
            }
#pragma unroll
            for (int mt = 0; mt < 2; mt++)
#pragma unroll
                for (int nt = 0; nt < 6; nt++) {
                    mma16816(acc[mt][nt], ahf[mt], bhf[nt]);
                    mma16816(acc[mt][nt], ahf[mt], blf[nt]);
                    mma16816(acc[mt][nt], alf[mt], bhf[nt]);
                }
        }

        if (nxt < NTILES) {
            char* nAh = Abase + ((it + 1) & 1) * 2 * ABUF;
            char* nAl = nAh + ABUF;
#pragma unroll
            for (int q = 0; q < NPF; q++) {
                int idx = tid + 256 * q;
                int row = idx / (K / 4), k = (idx % (K / 4)) * 4;
                float4 v = pfA[q];
                int byte = (row * P + k) * 2;
                *(uint2*)(nAh + byte) = make_uint2(packhi(v.x, v.y), packhi(v.z, v.w));
                *(uint2*)(nAl + byte) = make_uint2(packlo(v.x, v.y), packlo(v.z, v.w));
            }
        }

#pragma unroll
        for (int mt = 0; mt < 2; mt++) {
            long r0 = tile * 64 + mrow + mt * 16 + g;
#pragma unroll
            for (int nt = 0; nt < 6; nt++) {
                int col = ncol + nt * 8 + 2 * cp;
                *(float2*)(OUT + r0 * G3 + col) =
                    make_float2(acc[mt][nt][0] + breg[nt][0], acc[mt][nt][1] + breg[nt][1]);
                *(float2*)(OUT + (r0 + 8) * G3 + col) =
                    make_float2(acc[mt][nt][2] + breg[nt][0], acc[mt][nt][3] + breg[nt][1]);
            }
        }
        __syncthreads();
    }
}

// ============================================================ fused 2-layer scan
// CTA = 32 batch rows, 256 threads, grid 128 (1 CTA/SM).
// One-step lag: at step t, layer1 computes h1[t], layer2 computes h2[t-1].
// Per step one MMA phase with 3 independent GEMMs (N=192, K=64, bf16 3-term):
//   gh1 = Whh0·h1[t-1], gx2 = Wih1·h1[t-1] (shares A-frags!), gh2 = Whh1·h2[t-2].
// Weights in SMEM as 16B fragment chunks [n][kc][cp] = {hi2,hi2,lo2,lo2},
// XOR-swizzled by row parity -> 1 conflict-free LDS.128 per fragment.
// Layer2 r,z gates use a SUMMED gx2+gh2 accumulator; n-gate keeps them split
// (PyTorch GRU: n = tanh(gxn + r*ghn)).
#define BBF 32
#define NTF 256
#define PAB 144
#define PG  196
#define P2S 132
#define P2N 68

#define WMAT_BYTES (192 * 256)                 // 49152 per matrix
#define OFF_A1H (3 * WMAT_BYTES)               // 147456
#define OFF_A1L (OFF_A1H + BBF * PAB)
#define OFF_A2H (OFF_A1L + BBF * PAB)
#define OFF_A2L (OFF_A2H + BBF * PAB)
#define OFF_G1  (OFF_A2L + BBF * PAB)          // fp32 [32][PG]
#define OFF_G2S (OFF_G1 + BBF * PG * 4)        // fp32 [32][P2S] cols 0..127 summed
#define OFF_G2X (OFF_G2S + BBF * P2S * 4)      // fp32 [32][P2N] n-gate gx2
#define OFF_G2H (OFF_G2X + BBF * P2N * 4)      // fp32 [32][P2N] n-gate gh2
#define SMF_TOTAL (OFF_G2H + BBF * P2N * 4)    // 225280 bytes

__device__ __forceinline__ uint4 ldw(const char* sWm, int n, int kc, int cp) {
    int phys = (kc * 4 + cp) ^ ((n & 1) * 4);
    return *(const uint4*)(sWm + n * 256 + phys * 16);
}

__global__ __launch_bounds__(NTF, 1)
void gru_fused(const float* __restrict__ GX,    // [MTOT][G3] gx1 (incl bih0)
               const float* __restrict__ Whh0,
               const float* __restrict__ bhh0,
               const float* __restrict__ Wih1,
               const float* __restrict__ bih1,
               const float* __restrict__ Whh1,
               const float* __restrict__ bhh1,
               const float* __restrict__ Wfc,
               const float* __restrict__ bfc,
               float* __restrict__ out)
{
    extern __shared__ char sm[];
    char*  sW0 = sm;
    char*  sW1 = sm + WMAT_BYTES;
    char*  sW2 = sm + 2 * WMAT_BYTES;
    char*  sA1h = sm + OFF_A1H;
    char*  sA1l = sm + OFF_A1L;
    char*  sA2h = sm + OFF_A2H;
    char*  sA2l = sm + OFF_A2L;
    float* sG1  = (float*)(sm + OFF_G1);
    float* sG2s = (float*)(sm + OFF_G2S);
    float* sG2x = (float*)(sm + OFF_G2X);
    float* sG2h = (float*)(sm + OFF_G2H);

    const int tid = threadIdx.x;
    const int wid = tid >> 5;
    const int lid = tid & 31;
    const int g   = lid >> 2;
    const int cp  = lid & 3;
    const int b0  = blockIdx.x * BBF;

    // ---- stage all 3 weight matrices as fragment chunks ----
    {
        const float* Ws[3] = {Whh0, Wih1, Whh1};
        for (int c = tid; c < 3 * 192 * 16; c += NTF) {
            int m   = c / (192 * 16);
            int rem = c % (192 * 16);
            int n   = rem >> 4;
            int ci  = rem & 15;               // logical chunk = kc*4 + cp
            int kc  = ci >> 2, cpp = ci & 3;
            const float* Wr = Ws[m] + n * HID + kc * 16 + 2 * cpp;
            float2 a = *(const float2*)(Wr);
            float2 b = *(const float2*)(Wr + 8);
            uint4 ch;
            ch.x = packhi(a.x, a.y); ch.y = packhi(b.x, b.y);
            ch.z = packlo(a.x, a.y); ch.w = packlo(b.x, b.y);
            int phys = ci ^ ((n & 1) * 4);
            *(uint4*)(sm + m * WMAT_BYTES + n * 256 + phys * 16) = ch;
        }
    }
    // zero h tiles
    for (int i = tid; i < BBF * PAB; i += NTF) {
        sA1h[i] = 0; sA1l[i] = 0; sA2h[i] = 0; sA2l[i] = 0;
    }

    // ---- MMA-side identity ----
    const int mrow = (wid & 1) * 16;
    const int ncol = (wid >> 1) * 48;

    float bh1v[6][2], b2xv[6][2], b2hv[6][2];
#pragma unroll
    for (int nt = 0; nt < 6; nt++) {
        int col = ncol + nt * 8 + 2 * cp;
        bh1v[nt][0] = bhh0[col]; bh1v[nt][1] = bhh0[col + 1];
        b2xv[nt][0] = bih1[col]; b2xv[nt][1] = bih1[col + 1];
        b2hv[nt][0] = bhh1[col]; b2hv[nt][1] = bhh1[col + 1];
    }

    // ---- gate-side identity: row = tid>>3, 8 units at (tid&7)*8 ----
    const int grow = tid >> 3;
    const int u0   = (tid & 7) * 8;
    const long gxrow0 = ((long)(b0 + grow) * SEQT) * G3 + u0;

    float wfc[8];
#pragma unroll
    for (int s = 0; s < 8; s++) wfc[s] = Wfc[u0 + s];

    float h1r[8], h2r[8];
#pragma unroll
    for (int s = 0; s < 8; s++) { h1r[s] = 0.0f; h2r[s] = 0.0f; }

    __syncthreads();

    // prefetch gx1(t=0)
    float4 pf[6];
#pragma unroll
    for (int g3 = 0; g3 < 3; g3++) {
        pf[g3 * 2]     = *(const float4*)(GX + gxrow0 + g3 * 64);
        pf[g3 * 2 + 1] = *(const float4*)(GX + gxrow0 + g3 * 64 + 4);
    }

    for (int t = 0; t <= SEQT; t++) {
        // ============ MMA phase: gh1, gx2, gh2 ============
        float a1[6][4], a2x[6][4], a2h[6][4];
#pragma unroll
        for (int nt = 0; nt < 6; nt++) {
            a1[nt][0] = bh1v[nt][0]; a1[nt][1] = bh1v[nt][1];
            a1[nt][2] = bh1v[nt][0]; a1[nt][3] = bh1v[nt][1];
            a2x[nt][0] = b2xv[nt][0]; a2x[nt][1] = b2xv[nt][1];
            a2x[nt][2] = b2xv[nt][0]; a2x[nt][3] = b2xv[nt][1];
            a2h[nt][0] = b2hv[nt][0]; a2h[nt][1] = b2hv[nt][1];
            a2h[nt][2] = b2hv[nt][0]; a2h[nt][3] = b2hv[nt][1];
        }
#pragma unroll
        for (int kc = 0; kc < 4; kc++) {
            const int kb = kc * 16;
            u32 a1hf[4], a1lf[4], a2hf[4], a2lf[4];
            {
                int c0b = (mrow + g) * PAB + (kb + 2 * cp) * 2;
                int c1b = (mrow + g + 8) * PAB + (kb + 2 * cp) * 2;
                a1hf[0] = *(const u32*)(sA1h + c0b);
                a1hf[1] = *(const u32*)(sA1h + c1b);
                a1hf[2] = *(const u32*)(sA1h + c0b + 16);
                a1hf[3] = *(const u32*)(sA1h + c1b + 16);
                a1lf[0] = *(const u32*)(sA1l + c0b);
                a1lf[1] = *(const u32*)(sA1l + c1b);
                a1lf[2] = *(const u32*)(sA1l + c0b + 16);
                a1lf[3] = *(const u32*)(sA1l + c1b + 16);
                a2hf[0] = *(const u32*)(sA2h + c0b);
                a2hf[1] = *(const u32*)(sA2h + c1b);
                a2hf[2] = *(const u32*)(sA2h + c0b + 16);
                a2hf[3] = *(const u32*)(sA2h + c1b + 16);
                a2lf[0] = *(const u32*)(sA2l + c0b);
                a2lf[1] = *(const u32*)(sA2l + c1b);
                a2lf[2] = *(const u32*)(sA2l + c0b + 16);
                a2lf[3] = *(const u32*)(sA2l + c1b + 16);
            }
#pragma unroll
            for (int nt = 0; nt < 6; nt++) {
                int n = ncol + nt * 8 + g;
                mma3(a1[nt],  a1hf, a1lf, ldw(sW0, n, kc, cp));   // gh1 = Whh0·h1
                mma3(a2x[nt], a1hf, a1lf, ldw(sW1, n, kc, cp));   // gx2 = Wih1·h1
                mma3(a2h[nt], a2hf, a2lf, ldw(sW2, n, kc, cp));   // gh2 = Whh1·h2
            }
        }
        // ---- stage ----
#pragma unroll
        for (int nt = 0; nt < 6; nt++) {
            int tcol = ncol + nt * 8;
            int col  = tcol + 2 * cp;
            *(float2*)(sG1 + (mrow + g) * PG + col)     = make_float2(a1[nt][0], a1[nt][1]);
            *(float2*)(sG1 + (mrow + g + 8) * PG + col) = make_float2(a1[nt][2], a1[nt][3]);
            if (tcol < 128) {
                *(float2*)(sG2s + (mrow + g) * P2S + col) =
                    make_float2(a2x[nt][0] + a2h[nt][0], a2x[nt][1] + a2h[nt][1]);
                *(float2*)(sG2s + (mrow + g + 8) * P2S + col) =
                    make_float2(a2x[nt][2] + a2h[nt][2], a2x[nt][3] + a2h[nt][3]);
            } else {
                int nc = col - 128;
                *(float2*)(sG2x + (mrow + g) * P2N + nc)     = make_float2(a2x[nt][0], a2x[nt][1]);
                *(float2*)(sG2x + (mrow + g + 8) * P2N + nc) = make_float2(a2x[nt][2], a2x[nt][3]);
                *(float2*)(sG2h + (mrow + g) * P2N + nc)     = make_float2(a2h[nt][0], a2h[nt][1]);
                *(float2*)(sG2h + (mrow + g + 8) * P2N + nc) = make_float2(a2h[nt][2], a2h[nt][3]);
            }
        }
        __syncthreads();

        // ============ gate phase ============
        if (t < SEQT) {               // layer 1 -> h1[t]
            const float* gr = sG1 + grow * PG + u0;
            float4 r0 = *(const float4*)(gr);
            float4 r1 = *(const float4*)(gr + 4);
            float4 z0 = *(const float4*)(gr + 64);
            float4 z1 = *(const float4*)(gr + 68);
            float4 n0 = *(const float4*)(gr + 128);
            float4 n1 = *(const float4*)(gr + 132);
            float ghr[8] = {r0.x, r0.y, r0.z, r0.w, r1.x, r1.y, r1.z, r1.w};
            float ghz[8] = {z0.x, z0.y, z0.z, z0.w, z1.x, z1.y, z1.z, z1.w};
            float ghn[8] = {n0.x, n0.y, n0.z, n0.w, n1.x, n1.y, n1.z, n1.w};
            float gxr[8] = {pf[0].x, pf[0].y, pf[0].z, pf[0].w, pf[1].x, pf[1].y, pf[1].z, pf[1].w};
            float gxz[8] = {pf[2].x, pf[2].y, pf[2].z, pf[2].w, pf[3].x, pf[3].y, pf[3].z, pf[3].w};
            float gxn[8] = {pf[4].x, pf[4].y, pf[4].z, pf[4].w, pf[5].x, pf[5].y, pf[5].z, pf[5].w};

            float h[8];
#pragma unroll
            for (int s = 0; s < 8; s++) {
                float rg = siga(gxr[s] + ghr[s]);
                float zg = siga(gxz[s] + ghz[s]);
                float ng = tanha(gxn[s] + rg * ghn[s]);
                h[s] = ng + zg * (h1r[s] - ng);
                h1r[s] = h[s];
            }
            int abyte = grow * PAB + u0 * 2;
            *(uint4*)(sA1h + abyte) = make_uint4(packhi(h[0], h[1]), packhi(h[2], h[3]),
                                                 packhi(h[4], h[5]), packhi(h[6], h[7]));
            *(uint4*)(sA1l + abyte) = make_uint4(packlo(h[0], h[1]), packlo(h[2], h[3]),
                                                 packlo(h[4], h[5]), packlo(h[6], h[7]));
            if (t + 1 < SEQT) {
                const float* gp = GX + gxrow0 + (long)(t + 1) * G3;
#pragma unroll
                for (int g3 = 0; g3 < 3; g3++) {
                    pf[g3 * 2]     = *(const float4*)(gp + g3 * 64);
                    pf[g3 * 2 + 1] = *(const float4*)(gp + g3 * 64 + 4);
                }
            }
        }
        if (t > 0) {                  // layer 2 -> h2[t-1]
            float4 rs0 = *(const float4*)(sG2s + grow * P2S + u0);
            float4 rs1 = *(const float4*)(sG2s + grow * P2S + u0 + 4);
            float4 zs0 = *(const float4*)(sG2s + grow * P2S + 64 + u0);
            float4 zs1 = *(const float4*)(sG2s + grow * P2S + 64 + u0 + 4);
            float4 xn0 = *(const float4*)(sG2x + grow * P2N + u0);
            float4 xn1 = *(const float4*)(sG2x + grow * P2N + u0 + 4);
            float4 hn0 = *(const float4*)(sG2h + grow * P2N + u0);
            float4 hn1 = *(const float4*)(sG2h + grow * P2N + u0 + 4);
            float sr[8] = {rs0.x, rs0.y, rs0.z, rs0.w, rs1.x, rs1.y, rs1.z, rs1.w};
            float sz[8] = {zs0.x, zs0.y, zs0.z, zs0.w, zs1.x, zs1.y, zs1.z, zs1.w};
            float xn[8] = {xn0.x, xn0.y, xn0.z, xn0.w, xn1.x, xn1.y, xn1.z, xn1.w};
            float hn[8] = {hn0.x, hn0.y, hn0.z, hn0.w, hn1.x, hn1.y, hn1.z, hn1.w};

            float h[8];
#pragma unroll
            for (int s = 0; s < 8; s++) {
                float rg = siga(sr[s]);
                float zg = siga(sz[s]);
                float ng = tanha(xn[s] + rg * hn[s]);
                h[s] = ng + zg * (h2r[s] - ng);
                h2r[s] = h[s];
            }
            int abyte = grow * PAB + u0 * 2;
            *(uint4*)(sA2h + abyte) = make_uint4(packhi(h[0], h[1]), packhi(h[2], h[3]),
                                                 packhi(h[4], h[5]), packhi(h[6], h[7]));
            *(uint4*)(sA2l + abyte) = make_uint4(packlo(h[0], h[1]), packlo(h[2], h[3]),
                                                 packlo(h[4], h[5]), packlo(h[6], h[7]));
        }
        __syncthreads();
    }

    // ---- FC on h2[SEQT-1] (in h2r): 8 consecutive threads share a row ----
    float s = 0.0f;
#pragma unroll
    for (int q = 0; q < 8; q++) s += h2r[q] * wfc[q];
    s += __shfl_xor_sync(0xFFFFFFFF, s, 1);
    s += __shfl_xor_sync(0xFFFFFFFF, s, 2);
    s += __shfl_xor_sync(0xFFFFFFFF, s, 4);
    if ((tid & 7) == 0) out[b0 + grow] = s + bfc[0];
}

// ================================================================= host
extern "C" void kernel_launch(void* const* d_in, const int* in_sizes, int n_in,
                              void* d_out, int out_size)
{
    const float* x    = (const float*)d_in[0];
    const float* Wih0 = (const float*)d_in[1];
    const float* Whh0 = (const float*)d_in[2];
    const float* bih0 = (const float*)d_in[3];
    const float* bhh0 = (const float*)d_in[4];
    const float* Wih1 = (const float*)d_in[5];
    const float* Whh1 = (const float*)d_in[6];
    const float* bih1 = (const float*)d_in[7];
    const float* bhh1 = (const float*)d_in[8];
    const float* Wfc  = (const float*)d_in[9];
    const float* bfc  = (const float*)d_in[10];
    float* out = (float*)d_out;

    float* gx;
    cudaGetSymbolAddress((void**)&gx, g_gx);

    const int smG1 = 2 * (G3 * (DIN0 + 8) * 2) + 4 * (64 * (DIN0 + 8) * 2);

    cudaFuncSetAttribute(proj_gemm<DIN0>, cudaFuncAttributeMaxDynamicSharedMemorySize, smG1);
    cudaFuncSetAttribute(gru_fused, cudaFuncAttributeMaxDynamicSharedMemorySize, SMF_TOTAL);

    proj_gemm<DIN0><<<148, 256, smG1>>>(x, Wih0, bih0, gx);
    gru_fused<<<BATCH / BBF, NTF, SMF_TOTAL>>>(gx, Whh0, bhh0, Wih1, bih1,
                                               Whh1, bhh1, Wfc, bfc, out);
}

// round 13
// speedup vs baseline: 1.0856x; 1.0856x over previous
#include <cuda_runtime.h>
#include <cuda_bf16.h>
#include <stdint.h>

#define BATCH 4096
#define SEQT  256
#define DIN0  128
#define HID   64
#define G3    192
#define MTOT  (BATCH * SEQT)   // 1048576 rows

// Scratch (static). g_gx holds gx1 (layer-1 x-preact + bih0), then is
// overwritten IN-PLACE by the l1 kernel with gx2 (layer-2 x-preact + bih1).
__device__ float g_gx[(long)MTOT * G3];

typedef unsigned long long u64;
typedef unsigned int u32;

// ---------------------------------------------------------------- common
__device__ __forceinline__ void mma16816(float* c, const u32* a, const u32* b) {
    asm volatile(
        "mma.sync.aligned.m16n8k16.row.col.f32.bf16.bf16.f32 "
        "{%0,%1,%2,%3}, {%4,%5,%6,%7}, {%8,%9}, {%0,%1,%2,%3};"
        : "+f"(c[0]), "+f"(c[1]), "+f"(c[2]), "+f"(c[3])
        : "r"(a[0]), "r"(a[1]), "r"(a[2]), "r"(a[3]), "r"(b[0]), "r"(b[1]));
}
__device__ __forceinline__ u32 packhi(float a, float b) {
    return ((u32)__bfloat16_as_ushort(__float2bfloat16(a)))
         | ((u32)__bfloat16_as_ushort(__float2bfloat16(b)) << 16);
}
__device__ __forceinline__ u32 packlo(float a, float b) {
    float al = a - __bfloat162float(__float2bfloat16(a));
    float bl = b - __bfloat162float(__float2bfloat16(b));
    return ((u32)__bfloat16_as_ushort(__float2bfloat16(al)))
         | ((u32)__bfloat16_as_ushort(__float2bfloat16(bl)) << 16);
}
__device__ __forceinline__ float tanha(float x) {
    float y;
    asm("tanh.approx.f32 %0, %1;" : "=f"(y) : "f"(x));
    return y;
}
__device__ __forceinline__ float siga(float x) {
    return fmaf(0.5f, tanha(0.5f * x), 0.5f);
}
// 3-term split-bf16 MMA; w = {hi(k0,k0+1), hi(k0+8,k0+9), lo(..), lo(..)}
__device__ __forceinline__ void mma3(float* acc, const u32* ah, const u32* al, uint4 w) {
    u32 wh[2] = {w.x, w.y};
    u32 wl[2] = {w.z, w.w};
    mma16816(acc, ah, wh);
    mma16816(acc, ah, wl);
    mma16816(acc, al, wh);
}
// weight chunk load (R12-verified layout+swizzle): [n][16 chunks of 16B]
__device__ __forceinline__ uint4 ldw(const char* sWm, int n, int kc, int cp) {
    int phys = (kc * 4 + cp) ^ ((n & 1) * 4);
    return *(const uint4*)(sWm + n * 256 + phys * 16);
}

// ================================================================= GEMM1
// gx1[m][n] = x[m]·Wih0[n] + bih0[n]  (R8 verbatim — proven)
template<int K>
__global__ __launch_bounds__(256, 1)
void proj_gemm(const float* __restrict__ X,
               const float* __restrict__ W,
               const float* __restrict__ bias,
               float* __restrict__ OUT)
{
    constexpr int P      = K + 8;
    constexpr int NTILES = MTOT / 64;
    constexpr int ABUF   = 64 * P * 2;
    constexpr int BBUF   = G3 * P * 2;
    constexpr int NPF    = K / 16;

    extern __shared__ char smem[];
    char* Bh    = smem;
    char* Bl    = Bh + BBUF;
    char* Abase = Bl + BBUF;

    const int tid = threadIdx.x;
    const int wid = tid >> 5;
    const int lid = tid & 31;
    const int g   = lid >> 2;
    const int cp  = lid & 3;
    const int GRID = gridDim.x;

    for (int c = tid; c < G3 * (K / 8); c += 256) {
        int row = c / (K / 8), k = (c % (K / 8)) * 8;
        const float4* src = (const float4*)(W + row * K + k);
        float4 v0 = src[0], v1 = src[1];
        int byte = (row * P + k) * 2;
        *(uint4*)(Bh + byte) = make_uint4(packhi(v0.x, v0.y), packhi(v0.z, v0.w),
                                          packhi(v1.x, v1.y), packhi(v1.z, v1.w));
        *(uint4*)(Bl + byte) = make_uint4(packlo(v0.x, v0.y), packlo(v0.z, v0.w),
                                          packlo(v1.x, v1.y), packlo(v1.z, v1.w));
    }

    const int mrow = (wid & 1) * 32;
    const int ncol = (wid >> 1) * 48;

    float breg[6][2];
#pragma unroll
    for (int nt = 0; nt < 6; nt++) {
        int col = ncol + nt * 8 + 2 * cp;
        breg[nt][0] = bias[col];
        breg[nt][1] = bias[col + 1];
    }

    float4 pfA[NPF];
    long tile0 = blockIdx.x;
    if (tile0 < NTILES) {
#pragma unroll
        for (int q = 0; q < NPF; q++) {
            int idx = tid + 256 * q;
            int row = idx / (K / 4), k = (idx % (K / 4)) * 4;
            pfA[q] = *(const float4*)(X + (tile0 * 64 + row) * K + k);
        }
        char* Ah = Abase;
        char* Al = Abase + ABUF;
#pragma unroll
        for (int q = 0; q < NPF; q++) {
            int idx = tid + 256 * q;
            int row = idx / (K / 4), k = (idx % (K / 4)) * 4;
            float4 v = pfA[q];
            int byte = (row * P + k) * 2;
            *(uint2*)(Ah + byte) = make_uint2(packhi(v.x, v.y), packhi(v.z, v.w));
            *(uint2*)(Al + byte) = make_uint2(packlo(v.x, v.y), packlo(v.z, v.w));
        }
    }
    __syncthreads();

    int it = 0;
    for (long tile = tile0; tile < NTILES; tile += GRID, it++) {
        const long nxt = tile + GRID;
        if (nxt < NTILES) {
#pragma unroll
            for (int q = 0; q < NPF; q++) {
                int idx = tid + 256 * q;
                int row = idx / (K / 4), k = (idx % (K / 4)) * 4;
                pfA[q] = *(const float4*)(X + (nxt * 64 + row) * K + k);
            }
        }

        char* Ah = Abase + (it & 1) * 2 * ABUF;
        char* Al = Ah + ABUF;

        float acc[2][6][4];
#pragma unroll
        for (int mt = 0; mt < 2; mt++)
#pragma unroll
            for (int nt = 0; nt < 6; nt++)
#pragma unroll
                for (int q = 0; q < 4; q++) acc[mt][nt][q] = 0.0f;

#pragma unroll
        for (int ks = 0; ks < K / 16; ks++) {
            const int kb = ks * 16;
            u32 ahf[2][4], alf[2][4];
#pragma unroll
            for (int mt = 0; mt < 2; mt++) {
                int r = mrow + mt * 16 + g;
                int c0b = (r * P + kb + 2 * cp) * 2;
                int c1b = ((r + 8) * P + kb + 2 * cp) * 2;
                ahf[mt][0] = *(const u32*)(Ah + c0b);
                ahf[mt][1] = *(const u32*)(Ah + c1b);
                ahf[mt][2] = *(const u32*)(Ah + c0b + 16);
                ahf[mt][3] = *(const u32*)(Ah + c1b + 16);
                alf[mt][0] = *(const u32*)(Al + c0b);
                alf[mt][1] = *(const u32*)(Al + c1b);
                alf[mt][2] = *(const u32*)(Al + c0b + 16);
                alf[mt][3] = *(const u32*)(Al + c1b + 16);
            }
            u32 bhf[6][2], blf[6][2];
#pragma unroll
            for (int nt = 0; nt < 6; nt++) {
                int n = ncol + nt * 8 + g;
                int bb = (n * P + kb + 2 * cp) * 2;
                bhf[nt][0] = *(const u32*)(Bh + bb);
                bhf[nt][1] = *(const u32*)(Bh + bb + 16);
                blf[nt][0] = *(const u32*)(Bl + bb);
                blf[nt][1] = *(const u32*)(Bl + bb + 16);
            }
#pragma unroll
            for (int mt = 0; mt < 2; mt++)
#pragma unroll
                for (int nt = 0; nt < 6; nt++) {
                    mma16816(acc[mt][nt], ahf[mt], bhf[nt]);
                    mma16816(acc[mt][nt], ahf[mt], blf[nt]);
                    mma16816(acc[mt][nt], alf[mt], bhf[nt]);
                }
        }

        if (nxt < NTILES) {
            char* nAh = Abase + ((it + 1) & 1) * 2 * ABUF;
            char* nAl = nAh + ABUF;
#pragma unroll
            for (int q = 0; q < NPF; q++) {
                int idx = tid + 256 * q;
                int row = idx / (K / 4), k = (idx % (K / 4)) * 4;
                float4 v = pfA[q];
                int byte = (row * P + k) * 2;
                *(uint2*)(nAh + byte) = make_uint2(packhi(v.x, v.y), packhi(v.z, v.w));
                *(uint2*)(nAl + byte) = make_uint2(packlo(v.x, v.y), packlo(v.z, v.w));
            }
        }

#pragma unroll
        for (int mt = 0; mt < 2; mt++) {
            long r0 = tile * 64 + mrow + mt * 16 + g;
#pragma unroll
            for (int nt = 0; nt < 6; nt++) {
                int col = ncol + nt * 8 + 2 * cp;
                *(float2*)(OUT + r0 * G3 + col) =
                    make_float2(acc[mt][nt][0] + breg[nt][0], acc[mt][nt][1] + breg[nt][1]);
                *(float2*)(OUT + (r0 + 8) * G3 + col) =
                    make_float2(acc[mt][nt][2] + breg[nt][0], acc[mt][nt][3] + breg[nt][1]);
            }
        }
        __syncthreads();
    }
}

// ============================================================ layer-1 scan + gx2 projection
// R8 recurrence structure (32 rows, 2 groups, named barriers, stagger), PLUS:
// the MMA phase also computes gx2 = Wih1·h1[t-1] + bih1 (SHARES A-fragments
// with gh1) and streams it to g_gx[.., t-1, ..] (in-place over gx1; safe:
// gx1[t] is consumed at gate phase t, two barriers before gx2[t] is written
// at MMA phase t+1; rows are CTA-private). Both weight matrices via the
// R12-verified SMEM chunk layout to keep regs < 160. Loop runs to t==SEQT
// so gx2[SEQT-1] (from h1[SEQT-1]) gets written.
#define BBR 32
#define NTR 256
#define PAB 144
#define PG  196

#define L1_W0  0
#define L1_W1  49152
#define L1_AH  98304
#define L1_AL  (L1_AH + BBR * PAB)
#define L1_GH  (L1_AL + BBR * PAB)
#define L1_TOTAL (L1_GH + BBR * PG * 4)        // 132608 B

__global__ __launch_bounds__(NTR, 1)
void gru_l1(const float* __restrict__ GXIO,    // [MTOT][G3] gx1 in, gx2 out (in-place)
            const float* __restrict__ Whh0,
            const float* __restrict__ bhh0,
            const float* __restrict__ Wih1,
            const float* __restrict__ bih1)
{
    extern __shared__ char sm[];
    char*  sW0 = sm + L1_W0;
    char*  sW1 = sm + L1_W1;
    char*  sAh = sm + L1_AH;
    char*  sAl = sm + L1_AL;
    float* sGh = (float*)(sm + L1_GH);

    const int tid = threadIdx.x;
    const int wid = tid >> 5;
    const int lid = tid & 31;
    const int g   = lid >> 2;
    const int cp  = lid & 3;
    const int b0  = blockIdx.x * BBR;

    const int grp  = wid >> 2;
    const int mrow = grp * 16;
    const int ncol = (wid & 3) * 48;

    // ---- stage both weight matrices as fragment chunks (R12 layout) ----
    {
        const float* Ws[2] = {Whh0, Wih1};
        for (int c = tid; c < 2 * 192 * 16; c += NTR) {
            int m   = c / (192 * 16);
            int rem = c % (192 * 16);
            int n   = rem >> 4;
            int ci  = rem & 15;
            int kc  = ci >> 2, cpp = ci & 3;
            const float* Wr = Ws[m] + n * HID + kc * 16 + 2 * cpp;
            float2 a = *(const float2*)(Wr);
            float2 b = *(const float2*)(Wr + 8);
            uint4 ch;
            ch.x = packhi(a.x, a.y); ch.y = packhi(b.x, b.y);
            ch.z = packlo(a.x, a.y); ch.w = packlo(b.x, b.y);
            int phys = ci ^ ((n & 1) * 4);
            *(uint4*)(sm + m * 49152 + n * 256 + phys * 16) = ch;
        }
    }

    float bhv[6][2], b2v[6][2];
#pragma unroll
    for (int nt = 0; nt < 6; nt++) {
        int col = ncol + nt * 8 + 2 * cp;
        bhv[nt][0] = bhh0[col]; bhv[nt][1] = bhh0[col + 1];
        b2v[nt][0] = bih1[col]; b2v[nt][1] = bih1[col + 1];
    }

    const int gtid = tid & 127;
    const int grow = mrow + (gtid >> 3);
    const int uc   = gtid & 7;
    const long gxrow0 = ((long)(b0 + grow) * SEQT) * G3 + uc * 8;

    float hreg[8];
#pragma unroll
    for (int s = 0; s < 8; s++) hreg[s] = 0.0f;

    for (int i = tid; i < BBR * PAB / 4; i += NTR) {
        ((u32*)sAh)[i] = 0u;
        ((u32*)sAl)[i] = 0u;
    }
    __syncthreads();

    float4 pf[6];
#pragma unroll
    for (int g3 = 0; g3 < 3; g3++) {
        pf[g3 * 2]     = *(const float4*)(GXIO + gxrow0 + g3 * 64);
        pf[g3 * 2 + 1] = *(const float4*)(GXIO + gxrow0 + g3 * 64 + 4);
    }

    if (grp == 1) __nanosleep(400);
    const u32 barid = grp + 1;

    for (int t = 0; t <= SEQT; t++) {
        // ======= MMA phase: gh1 = Whh0·h1[t-1], gx2 = Wih1·h1[t-1] =======
        float a1[6][4], a2[6][4];
#pragma unroll
        for (int nt = 0; nt < 6; nt++) {
            a1[nt][0] = bhv[nt][0]; a1[nt][1] = bhv[nt][1];
            a1[nt][2] = bhv[nt][0]; a1[nt][3] = bhv[nt][1];
            a2[nt][0] = b2v[nt][0]; a2[nt][1] = b2v[nt][1];
            a2[nt][2] = b2v[nt][0]; a2[nt][3] = b2v[nt][1];
        }
#pragma unroll
        for (int kc = 0; kc < 4; kc++) {
            const int kb = kc * 16;
            u32 ahf[4], alf[4];
            {
                int r = mrow + g;
                int c0b = r * PAB + (kb + 2 * cp) * 2;
                int c1b = (r + 8) * PAB + (kb + 2 * cp) * 2;
                ahf[0] = *(const u32*)(sAh + c0b);
                ahf[1] = *(const u32*)(sAh + c1b);
                ahf[2] = *(const u32*)(sAh + c0b + 16);
                ahf[3] = *(const u32*)(sAh + c1b + 16);
                alf[0] = *(const u32*)(sAl + c0b);
                alf[1] = *(const u32*)(sAl + c1b);
                alf[2] = *(const u32*)(sAl + c0b + 16);
                alf[3] = *(const u32*)(sAl + c1b + 16);
            }
#pragma unroll
            for (int nt = 0; nt < 6; nt++) {
                int n = ncol + nt * 8 + g;
                mma3(a1[nt], ahf, alf, ldw(sW0, n, kc, cp));
                mma3(a2[nt], ahf, alf, ldw(sW1, n, kc, cp));
            }
        }
        // gh1 -> SMEM staging (only needed while gates still run)
        if (t < SEQT) {
#pragma unroll
            for (int nt = 0; nt < 6; nt++) {
                int col = ncol + nt * 8 + 2 * cp;
                *(float2*)(sGh + (mrow + g) * PG + col) =
                    make_float2(a1[nt][0], a1[nt][1]);
                *(float2*)(sGh + (mrow + g + 8) * PG + col) =
                    make_float2(a1[nt][2], a1[nt][3]);
            }
        }
        // gx2 -> GMEM at time t-1 (from h1[t-1]); overlaps with barrier/gates
        if (t > 0) {
            long ra = (long)(b0 + mrow + g) * SEQT + (t - 1);
            long rb = (long)(b0 + mrow + g + 8) * SEQT + (t - 1);
#pragma unroll
            for (int nt = 0; nt < 6; nt++) {
                int col = ncol + nt * 8 + 2 * cp;
                *(float2*)(&g_gx[ra * G3 + col]) = make_float2(a2[nt][0], a2[nt][1]);
                *(float2*)(&g_gx[rb * G3 + col]) = make_float2(a2[nt][2], a2[nt][3]);
            }
        }
        asm volatile("bar.sync %0, 128;" :: "r"(barid) : "memory");

        // ======= gate phase: h1[t] =======
        if (t < SEQT) {
            const float* gr = sGh + grow * PG + uc * 8;
            float4 r0 = *(const float4*)(gr);
            float4 r1 = *(const float4*)(gr + 4);
            float4 z0 = *(const float4*)(gr + 64);
            float4 z1 = *(const float4*)(gr + 68);
            float4 n0 = *(const float4*)(gr + 128);
            float4 n1 = *(const float4*)(gr + 132);
            float ghr[8] = {r0.x, r0.y, r0.z, r0.w, r1.x, r1.y, r1.z, r1.w};
            float ghz[8] = {z0.x, z0.y, z0.z, z0.w, z1.x, z1.y, z1.z, z1.w};
            float ghn[8] = {n0.x, n0.y, n0.z, n0.w, n1.x, n1.y, n1.z, n1.w};
            float gxr[8] = {pf[0].x, pf[0].y, pf[0].z, pf[0].w, pf[1].x, pf[1].y, pf[1].z, pf[1].w};
            float gxz[8] = {pf[2].x, pf[2].y, pf[2].z, pf[2].w, pf[3].x, pf[3].y, pf[3].z, pf[3].w};
            float gxn[8] = {pf[4].x, pf[4].y, pf[4].z, pf[4].w, pf[5].x, pf[5].y, pf[5].z, pf[5].w};

            float h[8];
#pragma unroll
            for (int s = 0; s < 8; s++) {
                float rg = siga(gxr[s] + ghr[s]);
                float zg = siga(gxz[s] + ghz[s]);
                float ng = tanha(gxn[s] + rg * ghn[s]);
                h[s] = ng + zg * (hreg[s] - ng);
                hreg[s] = h[s];
            }
            int abyte = grow * PAB + uc * 16;
            *(uint4*)(sAh + abyte) = make_uint4(packhi(h[0], h[1]), packhi(h[2], h[3]),
                                                packhi(h[4], h[5]), packhi(h[6], h[7]));
            *(uint4*)(sAl + abyte) = make_uint4(packlo(h[0], h[1]), packlo(h[2], h[3]),
                                                packlo(h[4], h[5]), packlo(h[6], h[7]));
            if (t + 1 < SEQT) {
                const float* gp = GXIO + gxrow0 + (long)(t + 1) * G3;
#pragma unroll
                for (int g3 = 0; g3 < 3; g3++) {
                    pf[g3 * 2]     = *(const float4*)(gp + g3 * 64);
                    pf[g3 * 2 + 1] = *(const float4*)(gp + g3 * 64 + 4);
                }
            }
        }
        asm volatile("bar.sync %0, 128;" :: "r"(barid) : "memory");
    }
}

// ============================================================ layer-2 scan (R8 verbatim, FIRST=false)
__global__ __launch_bounds__(NTR, 1)
void gru_l2(const float* __restrict__ GX,      // [MTOT][G3] gx2 (incl bih1)
            const float* __restrict__ Whh,
            const float* __restrict__ bhh,
            const float* __restrict__ Wfc,
            const float* __restrict__ bfc,
            float* __restrict__ out)
{
    extern __shared__ char smemc[];
    char*  sAh = smemc;
    char*  sAl = sAh + BBR * PAB;
    float* sGh = (float*)(sAl + BBR * PAB);

    const int tid = threadIdx.x;
    const int wid = tid >> 5;
    const int lid = tid & 31;
    const int g   = lid >> 2;
    const int cp  = lid & 3;
    const int b0  = blockIdx.x * BBR;

    const int grp  = wid >> 2;
    const int mrow = grp * 16;
    const int ncol = (wid & 3) * 48;

    u32 bh[4][6][2], bl[4][6][2];
    float bhv[6][2];
#pragma unroll
    for (int nt = 0; nt < 6; nt++) {
        int n = ncol + nt * 8 + g;
#pragma unroll
        for (int kc = 0; kc < 4; kc++) {
            int k0 = kc * 16 + 2 * cp;
            float w0 = Whh[n * HID + k0],     w1 = Whh[n * HID + k0 + 1];
            float w2 = Whh[n * HID + k0 + 8], w3 = Whh[n * HID + k0 + 9];
            bh[kc][nt][0] = packhi(w0, w1);  bh[kc][nt][1] = packhi(w2, w3);
            bl[kc][nt][0] = packlo(w0, w1);  bl[kc][nt][1] = packlo(w2, w3);
        }
        int colc = ncol + nt * 8 + 2 * cp;
        bhv[nt][0] = bhh[colc];
        bhv[nt][1] = bhh[colc + 1];
    }

    const int gtid = tid & 127;
    const int grow = mrow + (gtid >> 3);
    const int uc   = gtid & 7;
    const long gxrow0 = ((long)(b0 + grow) * SEQT) * G3 + uc * 8;

    float wfc[8];
#pragma unroll
    for (int s = 0; s < 8; s++) wfc[s] = Wfc[uc * 8 + s];
    float hreg[8];
#pragma unroll
    for (int s = 0; s < 8; s++) hreg[s] = 0.0f;

    for (int i = tid; i < BBR * PAB / 4; i += NTR) {
        ((u32*)sAh)[i] = 0u;
        ((u32*)sAl)[i] = 0u;
    }
    __syncthreads();

    float4 pf[6];
#pragma unroll
    for (int g3 = 0; g3 < 3; g3++) {
        pf[g3 * 2]     = *(const float4*)(GX + gxrow0 + g3 * 64);
        pf[g3 * 2 + 1] = *(const float4*)(GX + gxrow0 + g3 * 64 + 4);
    }

    if (grp == 1) __nanosleep(400);
    const u32 barid = grp + 1;

    for (int t = 0; t < SEQT; t++) {
        float acc[6][4];
#pragma unroll
        for (int nt = 0; nt < 6; nt++)
#pragma unroll
            for (int q = 0; q < 4; q++) acc[nt][q] = 0.0f;

#pragma unroll
        for (int kc = 0; kc < 4; kc++) {
            const int kb = kc * 16;
            u32 ahf[4], alf[4];
            {
                int r = mrow + g;
                int c0b = r * PAB + (kb + 2 * cp) * 2;
                int c1b = (r + 8) * PAB + (kb + 2 * cp) * 2;
                ahf[0] = *(const u32*)(sAh + c0b);
                ahf[1] = *(const u32*)(sAh + c1b);
                ahf[2] = *(const u32*)(sAh + c0b + 16);
                ahf[3] = *(const u32*)(sAh + c1b + 16);
                alf[0] = *(const u32*)(sAl + c0b);
                alf[1] = *(const u32*)(sAl + c1b);
                alf[2] = *(const u32*)(sAl + c0b + 16);
                alf[3] = *(const u32*)(sAl + c1b + 16);
            }
#pragma unroll
            for (int nt = 0; nt < 6; nt++) {
                mma16816(acc[nt], ahf, bh[kc][nt]);
                mma16816(acc[nt], ahf, bl[kc][nt]);
                mma16816(acc[nt], alf, bh[kc][nt]);
            }
        }
#pragma unroll
        for (int nt = 0; nt < 6; nt++) {
            int col = ncol + nt * 8 + 2 * cp;
            *(float2*)(sGh + (mrow + g) * PG + col) =
                make_float2(acc[nt][0] + bhv[nt][0], acc[nt][1] + bhv[nt][1]);
            *(float2*)(sGh + (mrow + g + 8) * PG + col) =
                make_float2(acc[nt][2] + bhv[nt][0], acc[nt][3] + bhv[nt][1]);
        }
        asm volatile("bar.sync %0, 128;" :: "r"(barid) : "memory");

        {
            const float* gr = sGh + grow * PG + uc * 8;
            float4 r0 = *(const float4*)(gr);
            float4 r1 = *(const float4*)(gr + 4);
            float4 z0 = *(const float4*)(gr + 64);
            float4 z1 = *(const float4*)(gr + 68);
            float4 n0 = *(const float4*)(gr + 128);
            float4 n1 = *(const float4*)(gr + 132);
            float ghr[8] = {r0.x, r0.y, r0.z, r0.w, r1.x, r1.y, r1.z, r1.w};
            float ghz[8] = {z0.x, z0.y, z0.z, z0.w, z1.x, z1.y, z1.z, z1.w};
            float ghn[8] = {n0.x, n0.y, n0.z, n0.w, n1.x, n1.y, n1.z, n1.w};
            float gxr[8] = {pf[0].x, pf[0].y, pf[0].z, pf[0].w, pf[1].x, pf[1].y, pf[1].z, pf[1].w};
            float gxz[8] = {pf[2].x, pf[2].y, pf[2].z, pf[2].w, pf[3].x, pf[3].y, pf[3].z, pf[3].w};
            float gxn[8] = {pf[4].x, pf[4].y, pf[4].z, pf[4].w, pf[5].x, pf[5].y, pf[5].z, pf[5].w};

            float h[8];
#pragma unroll
            for (int s = 0; s < 8; s++) {
                float rg = siga(gxr[s] + ghr[s]);
                float zg = siga(gxz[s] + ghz[s]);
                float ng = tanha(gxn[s] + rg * ghn[s]);
                h[s] = ng + zg * (hreg[s] - ng);
                hreg[s] = h[s];
            }
            int abyte = grow * PAB + uc * 16;
            *(uint4*)(sAh + abyte) = make_uint4(packhi(h[0], h[1]), packhi(h[2], h[3]),
                                                packhi(h[4], h[5]), packhi(h[6], h[7]));
            *(uint4*)(sAl + abyte) = make_uint4(packlo(h[0], h[1]), packlo(h[2], h[3]),
                                                packlo(h[4], h[5]), packlo(h[6], h[7]));
            if (t + 1 < SEQT) {
                const float* gp = GX + gxrow0 + (long)(t + 1) * G3;
#pragma unroll
                for (int g3 = 0; g3 < 3; g3++) {
                    pf[g3 * 2]     = *(const float4*)(gp + g3 * 64);
                    pf[g3 * 2 + 1] = *(const float4*)(gp + g3 * 64 + 4);
                }
            }
        }
        asm volatile("bar.sync %0, 128;" :: "r"(barid) : "memory");
    }

    float s = 0.0f;
#pragma unroll
    for (int q = 0; q < 8; q++) s += hreg[q] * wfc[q];
    s += __shfl_xor_sync(0xFFFFFFFF, s, 1);
    s += __shfl_xor_sync(0xFFFFFFFF, s, 2);
    s += __shfl_xor_sync(0xFFFFFFFF, s, 4);
    if (uc == 0) out[b0 + grow] = s + bfc[0];
}

// ================================================================= host
extern "C" void kernel_launch(void* const* d_in, const int* in_sizes, int n_in,
                              void* d_out, int out_size)
{
    const float* x    = (const float*)d_in[0];
    const float* Wih0 = (const float*)d_in[1];
    const float* Whh0 = (const float*)d_in[2];
    const float* bih0 = (const float*)d_in[3];
    const float* bhh0 = (const float*)d_in[4];
    const float* Wih1 = (const float*)d_in[5];
    const float* Whh1 = (const float*)d_in[6];
    const float* bih1 = (const float*)d_in[7];
    const float* bhh1 = (const float*)d_in[8];
    const float* Wfc  = (const float*)d_in[9];
    const float* bfc  = (const float*)d_in[10];
    float* out = (float*)d_out;

    float* gx;
    cudaGetSymbolAddress((void**)&gx, g_gx);

    const int smG1 = 2 * (G3 * (DIN0 + 8) * 2) + 4 * (64 * (DIN0 + 8) * 2);
    const int smL2 = 2 * BBR * PAB + BBR * PG * 4;

    cudaFuncSetAttribute(proj_gemm<DIN0>, cudaFuncAttributeMaxDynamicSharedMemorySize, smG1);
    cudaFuncSetAttribute(gru_l1, cudaFuncAttributeMaxDynamicSharedMemorySize, L1_TOTAL);
    cudaFuncSetAttribute(gru_l2, cudaFuncAttributeMaxDynamicSharedMemorySize, smL2);

    proj_gemm<DIN0><<<148, 256, smG1>>>(x, Wih0, bih0, gx);
    gru_l1<<<BATCH / BBR, NTR, L1_TOTAL>>>(gx, Whh0, bhh0, Wih1, bih1);
    gru_l2<<<BATCH / BBR, NTR, smL2>>>(gx, Whh1, bhh1, Wfc, bfc, out);
}

// round 14
// speedup vs baseline: 1.0895x; 1.0036x over previous
#include <cuda_runtime.h>
#include <cuda_bf16.h>
#include <stdint.h>

#define BATCH 4096
#define SEQT  256
#define DIN0  128
#define HID   64
#define G3    192
#define MTOT  (BATCH * SEQT)   // 1048576 rows

// Scratch (static: no allocations allowed)
__device__ float g_gx[(long)MTOT * G3];   // fp32 gate preactivations incl b_ih (reused both layers)
__device__ float g_h1[(long)MTOT * HID];  // layer-1 hidden sequence

typedef unsigned long long u64;
typedef unsigned int u32;

// ---------------------------------------------------------------- common
__device__ __forceinline__ void mma16816(float* c, const u32* a, const u32* b) {
    asm volatile(
        "mma.sync.aligned.m16n8k16.row.col.f32.bf16.bf16.f32 "
        "{%0,%1,%2,%3}, {%4,%5,%6,%7}, {%8,%9}, {%0,%1,%2,%3};"
        : "+f"(c[0]), "+f"(c[1]), "+f"(c[2]), "+f"(c[3])
        : "r"(a[0]), "r"(a[1]), "r"(a[2]), "r"(a[3]), "r"(b[0]), "r"(b[1]));
}
__device__ __forceinline__ u32 packhi(float a, float b) {
    return ((u32)__bfloat16_as_ushort(__float2bfloat16(a)))
         | ((u32)__bfloat16_as_ushort(__float2bfloat16(b)) << 16);
}
__device__ __forceinline__ u32 packlo(float a, float b) {
    float al = a - __bfloat162float(__float2bfloat16(a));
    float bl = b - __bfloat162float(__float2bfloat16(b));
    return ((u32)__bfloat16_as_ushort(__float2bfloat16(al)))
         | ((u32)__bfloat16_as_ushort(__float2bfloat16(bl)) << 16);
}
__device__ __forceinline__ float tanha(float x) {
    float y;
    asm("tanh.approx.f32 %0, %1;" : "=f"(y) : "f"(x));
    return y;
}
__device__ __forceinline__ float siga(float x) {
    return fmaf(0.5f, tanha(0.5f * x), 0.5f);
}

// ================================================================= GEMM
// OUT[m][n] = sum_k X[m][k]·W[n][k] + bias[n], split-bf16 3-term HMMA.
// Persistent, M=64 tiles, double-buffered A. NEW: fragment-CHUNK smem layouts
// so每 fragment load is ONE LDS.128 (was 4-8 LDS.32):
//   A chunk [mt4][kc][g][cp] (hi buf + lo buf): uint4 = {a0,a1,a2,a3} frags
//   B chunk [kc][n][cp]: uint4 = {bh0,bh1,bl0,bl1}
// Both warp read patterns are 512B contiguous -> conflict-free.
template<int K>
__global__ __launch_bounds__(256, 1)
void proj_gemm(const float* __restrict__ X,
               const float* __restrict__ W,
               const float* __restrict__ bias,
               float* __restrict__ OUT)
{
    constexpr int NKC    = K / 16;            // k-chunks
    constexpr int NTILES = MTOT / 64;
    constexpr int BCHB   = NKC * 192 * 64;    // B chunk bytes (hi+lo packed)
    constexpr int ACHB   = 2048 * NKC;        // one A buffer (hi or lo)
    constexpr int NPF    = K / 16;            // float4 A-prefetch regs/thread

    extern __shared__ char smem[];
    char* Bc    = smem;                        // B chunks
    char* Abase = smem + BCHB;                 // [buf(2)][hi,lo] A chunks

    const int tid = threadIdx.x;
    const int wid = tid >> 5;
    const int lid = tid & 31;
    const int g   = lid >> 2;
    const int cp  = lid & 3;
    const int GRID = gridDim.x;

    // ---- stage B chunks once ----
    for (int c = tid; c < NKC * 192 * 4; c += 256) {
        int kc  = c / (192 * 4);
        int rem = c % (192 * 4);
        int n   = rem >> 2, cpp = rem & 3;
        const float* Wr = W + n * K + kc * 16 + 2 * cpp;
        float2 a = *(const float2*)(Wr);
        float2 b = *(const float2*)(Wr + 8);
        *(uint4*)(Bc + ((kc * 192 + n) * 4 + cpp) * 16) =
            make_uint4(packhi(a.x, a.y), packhi(b.x, b.y),
                       packlo(a.x, a.y), packlo(b.x, b.y));
    }

    const int mrow = (wid & 1) * 32;
    const int ncol = (wid >> 1) * 48;

    float breg[6][2];
#pragma unroll
    for (int nt = 0; nt < 6; nt++) {
        int col = ncol + nt * 8 + 2 * cp;
        breg[nt][0] = bias[col];
        breg[nt][1] = bias[col + 1];
    }

    // stage one float4 (row, k..k+3) into chunked A buffers
    auto stageA = [&](char* Ah, char* Al, int row, int k, float4 v) {
        int mt4 = row >> 4, gg = row & 7, half = (row >> 3) & 1;
#pragma unroll
        for (int pi = 0; pi < 2; pi++) {
            int kp = k + 2 * pi;
            float a = pi ? v.z : v.x;
            float b = pi ? v.w : v.y;
            int kc = kp >> 4, rem = kp & 15;
            int cpp = (rem & 7) >> 1;
            int word = half + ((rem & 8) ? 2 : 0);
            int off = (((mt4 * NKC + kc) * 8 + gg) * 4 + cpp) * 16 + word * 4;
            *(u32*)(Ah + off) = packhi(a, b);
            *(u32*)(Al + off) = packlo(a, b);
        }
    };

    float4 pfA[NPF];
    long tile0 = blockIdx.x;
    if (tile0 < NTILES) {
#pragma unroll
        for (int q = 0; q < NPF; q++) {
            int idx = tid + 256 * q;
            int row = idx / (K / 4), k = (idx % (K / 4)) * 4;
            pfA[q] = *(const float4*)(X + (tile0 * 64 + row) * K + k);
        }
        char* Ah = Abase;
        char* Al = Abase + ACHB;
#pragma unroll
        for (int q = 0; q < NPF; q++) {
            int idx = tid + 256 * q;
            int row = idx / (K / 4), k = (idx % (K / 4)) * 4;
            stageA(Ah, Al, row, k, pfA[q]);
        }
    }
    __syncthreads();

    int it = 0;
    for (long tile = tile0; tile < NTILES; tile += GRID, it++) {
        const long nxt = tile + GRID;
        if (nxt < NTILES) {
#pragma unroll
            for (int q = 0; q < NPF; q++) {
                int idx = tid + 256 * q;
                int row = idx / (K / 4), k = (idx % (K / 4)) * 4;
                pfA[q] = *(const float4*)(X + (nxt * 64 + row) * K + k);
            }
        }

        char* Ah = Abase + (it & 1) * 2 * ACHB;
        char* Al = Ah + ACHB;

        float acc[2][6][4];
#pragma unroll
        for (int mt = 0; mt < 2; mt++)
#pragma unroll
            for (int nt = 0; nt < 6; nt++)
#pragma unroll
                for (int q = 0; q < 4; q++) acc[mt][nt][q] = 0.0f;

#pragma unroll
        for (int ks = 0; ks < NKC; ks++) {
            u32 ahf[2][4], alf[2][4];
#pragma unroll
            for (int mt = 0; mt < 2; mt++) {
                int mt4 = (wid & 1) * 2 + mt;
                int off = (((mt4 * NKC + ks) * 8 + g) * 4 + cp) * 16;
                uint4 h4 = *(const uint4*)(Ah + off);
                uint4 l4 = *(const uint4*)(Al + off);
                ahf[mt][0] = h4.x; ahf[mt][1] = h4.y; ahf[mt][2] = h4.z; ahf[mt][3] = h4.w;
                alf[mt][0] = l4.x; alf[mt][1] = l4.y; alf[mt][2] = l4.z; alf[mt][3] = l4.w;
            }
            u32 bhf[6][2], blf[6][2];
#pragma unroll
            for (int nt = 0; nt < 6; nt++) {
                int n = ncol + nt * 8 + g;
                uint4 wb = *(const uint4*)(Bc + ((ks * 192 + n) * 4 + cp) * 16);
                bhf[nt][0] = wb.x; bhf[nt][1] = wb.y;
                blf[nt][0] = wb.z; blf[nt][1] = wb.w;
            }
#pragma unroll
            for (int mt = 0; mt < 2; mt++)
#pragma unroll
                for (int nt = 0; nt < 6; nt++) {
                    mma16816(acc[mt][nt], ahf[mt], bhf[nt]);   // AhBh
                    mma16816(acc[mt][nt], ahf[mt], blf[nt]);   // AhBl
                    mma16816(acc[mt][nt], alf[mt], bhf[nt]);   // AlBh
                }
        }

        // stage next tile first (fills tensor-idle gap), then epilogue STGs drain
        if (nxt < NTILES) {
            char* nAh = Abase + ((it + 1) & 1) * 2 * ACHB;
            char* nAl = nAh + ACHB;
#pragma unroll
            for (int q = 0; q < NPF; q++) {
                int idx = tid + 256 * q;
                int row = idx / (K / 4), k = (idx % (K / 4)) * 4;
                stageA(nAh, nAl, row, k, pfA[q]);
            }
        }

#pragma unroll
        for (int mt = 0; mt < 2; mt++) {
            long r0 = tile * 64 + mrow + mt * 16 + g;
#pragma unroll
            for (int nt = 0; nt < 6; nt++) {
                int col = ncol + nt * 8 + 2 * cp;
                *(float2*)(OUT + r0 * G3 + col) =
                    make_float2(acc[mt][nt][0] + breg[nt][0], acc[mt][nt][1] + breg[nt][1]);
                *(float2*)(OUT + (r0 + 8) * G3 + col) =
                    make_float2(acc[mt][nt][2] + breg[nt][0], acc[mt][nt][3] + breg[nt][1]);
            }
        }
        __syncthreads();
    }
}

// ============================================================ recurrence (HMMA) — R8 verbatim (best: 1437)
// 32 rows in TWO independent 16-row groups (warps 0-3 / 4-7), named barriers
// + nanosleep stagger; warp tile m16 x n48; W_hh in B-fragment registers
// (hi/lo bf16, 3-term); gh staged via SMEM; gates tanh.approx.
#define BBR 32
#define NTR 256
#define PAB 144
#define PG  196

template<bool FIRST>
__global__ __launch_bounds__(NTR, 1)
void gru_hmma(const float* __restrict__ GX,
              const float* __restrict__ Whh,
              const float* __restrict__ bhh,
              const float* __restrict__ Wfc,
              const float* __restrict__ bfc,
              float* __restrict__ hout,
              float* __restrict__ out)
{
    extern __shared__ char smemc[];
    char*  sAh = smemc;
    char*  sAl = sAh + BBR * PAB;
    float* sGh = (float*)(sAl + BBR * PAB);

    const int tid = threadIdx.x;
    const int wid = tid >> 5;
    const int lid = tid & 31;
    const int g   = lid >> 2;
    const int cp  = lid & 3;
    const int b0  = blockIdx.x * BBR;

    const int grp  = wid >> 2;
    const int mrow = grp * 16;
    const int ncol = (wid & 3) * 48;

    u32 bh[4][6][2], bl[4][6][2];
    float bhv[6][2];
#pragma unroll
    for (int nt = 0; nt < 6; nt++) {
        int n = ncol + nt * 8 + g;
#pragma unroll
        for (int kc = 0; kc < 4; kc++) {
            int k0 = kc * 16 + 2 * cp;
            float w0 = Whh[n * HID + k0],     w1 = Whh[n * HID + k0 + 1];
            float w2 = Whh[n * HID + k0 + 8], w3 = Whh[n * HID + k0 + 9];
            bh[kc][nt][0] = packhi(w0, w1);  bh[kc][nt][1] = packhi(w2, w3);
            bl[kc][nt][0] = packlo(w0, w1);  bl[kc][nt][1] = packlo(w2, w3);
        }
        int colc = ncol + nt * 8 + 2 * cp;
        bhv[nt][0] = bhh[colc];
        bhv[nt][1] = bhh[colc + 1];
    }

    const int gtid = tid & 127;
    const int grow = mrow + (gtid >> 3);
    const int uc   = gtid & 7;
    const long gxrow0 = ((long)(b0 + grow) * SEQT) * G3 + uc * 8;

    float wfc[8];
    if (!FIRST) {
#pragma unroll
        for (int s = 0; s < 8; s++) wfc[s] = Wfc[uc * 8 + s];
    }
    float hreg[8];
#pragma unroll
    for (int s = 0; s < 8; s++) hreg[s] = 0.0f;

    for (int i = tid; i < BBR * PAB / 4; i += NTR) {
        ((u32*)sAh)[i] = 0u;
        ((u32*)sAl)[i] = 0u;
    }
    __syncthreads();

    float4 pf[6];
#pragma unroll
    for (int g3 = 0; g3 < 3; g3++) {
        pf[g3 * 2]     = *(const float4*)(GX + gxrow0 + g3 * 64);
        pf[g3 * 2 + 1] = *(const float4*)(GX + gxrow0 + g3 * 64 + 4);
    }

    if (grp == 1) __nanosleep(400);
    const u32 barid = grp + 1;

    for (int t = 0; t < SEQT; t++) {
        float acc[6][4];
#pragma unroll
        for (int nt = 0; nt < 6; nt++)
#pragma unroll
            for (int q = 0; q < 4; q++) acc[nt][q] = 0.0f;

#pragma unroll
        for (int kc = 0; kc < 4; kc++) {
            const int kb = kc * 16;
            u32 ahf[4], alf[4];
            {
                int r = mrow + g;
                int c0b = r * PAB + (kb + 2 * cp) * 2;
                int c1b = (r + 8) * PAB + (kb + 2 * cp) * 2;
                ahf[0] = *(const u32*)(sAh + c0b);
                ahf[1] = *(const u32*)(sAh + c1b);
                ahf[2] = *(const u32*)(sAh + c0b + 16);
                ahf[3] = *(const u32*)(sAh + c1b + 16);
                alf[0] = *(const u32*)(sAl + c0b);
                alf[1] = *(const u32*)(sAl + c1b);
                alf[2] = *(const u32*)(sAl + c0b + 16);
                alf[3] = *(const u32*)(sAl + c1b + 16);
            }
#pragma unroll
            for (int nt = 0; nt < 6; nt++) {
                mma16816(acc[nt], ahf, bh[kc][nt]);
                mma16816(acc[nt], ahf, bl[kc][nt]);
                mma16816(acc[nt], alf, bh[kc][nt]);
            }
        }
#pragma unroll
        for (int nt = 0; nt < 6; nt++) {
            int col = ncol + nt * 8 + 2 * cp;
            *(float2*)(sGh + (mrow + g) * PG + col) =
                make_float2(acc[nt][0] + bhv[nt][0], acc[nt][1] + bhv[nt][1]);
            *(float2*)(sGh + (mrow + g + 8) * PG + col) =
                make_float2(acc[nt][2] + bhv[nt][0], acc[nt][3] + bhv[nt][1]);
        }
        asm volatile("bar.sync %0, 128;" :: "r"(barid) : "memory");

        {
            const float* gr = sGh + grow * PG + uc * 8;
            float4 r0 = *(const float4*)(gr);
            float4 r1 = *(const float4*)(gr + 4);
            float4 z0 = *(const float4*)(gr + 64);
            float4 z1 = *(const float4*)(gr + 68);
            float4 n0 = *(const float4*)(gr + 128);
            float4 n1 = *(const float4*)(gr + 132);
            float ghr[8] = {r0.x, r0.y, r0.z, r0.w, r1.x, r1.y, r1.z, r1.w};
            float ghz[8] = {z0.x, z0.y, z0.z, z0.w, z1.x, z1.y, z1.z, z1.w};
            float ghn[8] = {n0.x, n0.y, n0.z, n0.w, n1.x, n1.y, n1.z, n1.w};
            float gxr[8] = {pf[0].x, pf[0].y, pf[0].z, pf[0].w, pf[1].x, pf[1].y, pf[1].z, pf[1].w};
            float gxz[8] = {pf[2].x, pf[2].y, pf[2].z, pf[2].w, pf[3].x, pf[3].y, pf[3].z, pf[3].w};
            float gxn[8] = {pf[4].x, pf[4].y, pf[4].z, pf[4].w, pf[5].x, pf[5].y, pf[5].z, pf[5].w};

            float h[8];
#pragma unroll
            for (int s = 0; s < 8; s++) {
                float rg = siga(gxr[s] + ghr[s]);
                float zg = siga(gxz[s] + ghz[s]);
                float ng = tanha(gxn[s] + rg * ghn[s]);
                h[s] = ng + zg * (hreg[s] - ng);
                hreg[s] = h[s];
            }
            int abyte = grow * PAB + uc * 16;
            *(uint4*)(sAh + abyte) = make_uint4(packhi(h[0], h[1]), packhi(h[2], h[3]),
                                                packhi(h[4], h[5]), packhi(h[6], h[7]));
            *(uint4*)(sAl + abyte) = make_uint4(packlo(h[0], h[1]), packlo(h[2], h[3]),
                                                packlo(h[4], h[5]), packlo(h[6], h[7]));
            if (FIRST) {
                float* hp = hout + ((long)(b0 + grow) * SEQT + t) * HID + uc * 8;
                *(float4*)(hp)     = make_float4(h[0], h[1], h[2], h[3]);
                *(float4*)(hp + 4) = make_float4(h[4], h[5], h[6], h[7]);
            }
            if (t + 1 < SEQT) {
                const float* gp = GX + gxrow0 + (long)(t + 1) * G3;
#pragma unroll
                for (int g3 = 0; g3 < 3; g3++) {
                    pf[g3 * 2]     = *(const float4*)(gp + g3 * 64);
                    pf[g3 * 2 + 1] = *(const float4*)(gp + g3 * 64 + 4);
                }
            }
        }
        asm volatile("bar.sync %0, 128;" :: "r"(barid) : "memory");
    }

    if (!FIRST) {
        float s = 0.0f;
#pragma unroll
        for (int q = 0; q < 8; q++) s += hreg[q] * wfc[q];
        s += __shfl_xor_sync(0xFFFFFFFF, s, 1);
        s += __shfl_xor_sync(0xFFFFFFFF, s, 2);
        s += __shfl_xor_sync(0xFFFFFFFF, s, 4);
        if (uc == 0) out[b0 + grow] = s + bfc[0];
    }
}

// ================================================================= host
extern "C" void kernel_launch(void* const* d_in, const int* in_sizes, int n_in,
                              void* d_out, int out_size)
{
    const float* x    = (const float*)d_in[0];
    const float* Wih0 = (const float*)d_in[1];
    const float* Whh0 = (const float*)d_in[2];
    const float* bih0 = (const float*)d_in[3];
    const float* bhh0 = (const float*)d_in[4];
    const float* Wih1 = (const float*)d_in[5];
    const float* Whh1 = (const float*)d_in[6];
    const float* bih1 = (const float*)d_in[7];
    const float* bhh1 = (const float*)d_in[8];
    const float* Wfc  = (const float*)d_in[9];
    const float* bfc  = (const float*)d_in[10];
    float* out = (float*)d_out;

    float *gx, *h1;
    cudaGetSymbolAddress((void**)&gx, g_gx);
    cudaGetSymbolAddress((void**)&h1, g_h1);

    // chunked smem: B chunks + 2x (hi+lo) A chunk buffers
    const int smG1 = (DIN0 / 16) * 192 * 64 + 4 * 2048 * (DIN0 / 16);   // 98304 + 65536
    const int smG2 = (HID  / 16) * 192 * 64 + 4 * 2048 * (HID  / 16);   // 49152 + 32768
    const int smR  = 2 * BBR * PAB + BBR * PG * 4;

    cudaFuncSetAttribute(proj_gemm<DIN0>, cudaFuncAttributeMaxDynamicSharedMemorySize, smG1);
    cudaFuncSetAttribute(proj_gemm<HID>,  cudaFuncAttributeMaxDynamicSharedMemorySize, smG2);
    cudaFuncSetAttribute(gru_hmma<true>,  cudaFuncAttributeMaxDynamicSharedMemorySize, smR);
    cudaFuncSetAttribute(gru_hmma<false>, cudaFuncAttributeMaxDynamicSharedMemorySize, smR);

    proj_gemm<DIN0><<<148, 256, smG1>>>(x, Wih0, bih0, gx);
    gru_hmma<true><<<BATCH / BBR, NTR, smR>>>(gx, Whh0, bhh0, nullptr, nullptr, h1, nullptr);
    proj_gemm<HID><<<296, 256, smG2>>>(h1, Wih1, bih1, gx);
    gru_hmma<false><<<BATCH / BBR, NTR, smR>>>(gx, Whh1, bhh1, Wfc, bfc, nullptr, out);
}

// round 15
// speedup vs baseline: 1.3952x; 1.2806x over previous
#include <cuda_runtime.h>
#include <cuda_bf16.h>
#include <cuda_fp16.h>
#include <stdint.h>

#define BATCH 4096
#define SEQT  256
#define DIN0  128
#define HID   64
#define G3    192
#define MTOT  (BATCH * SEQT)   // 1048576 rows

// Scratch (static: no allocations allowed)
__device__ float g_gx[(long)MTOT * G3];   // fp32 gate preactivations incl b_ih (reused both layers)
__device__ float g_h1[(long)MTOT * HID];  // layer-1 hidden sequence

typedef unsigned long long u64;
typedef unsigned int u32;

// ---------------------------------------------------------------- common
__device__ __forceinline__ void mma16816(float* c, const u32* a, const u32* b) {
    asm volatile(
        "mma.sync.aligned.m16n8k16.row.col.f32.bf16.bf16.f32 "
        "{%0,%1,%2,%3}, {%4,%5,%6,%7}, {%8,%9}, {%0,%1,%2,%3};"
        : "+f"(c[0]), "+f"(c[1]), "+f"(c[2]), "+f"(c[3])
        : "r"(a[0]), "r"(a[1]), "r"(a[2]), "r"(a[3]), "r"(b[0]), "r"(b[1]));
}
// fp16 variant (single-term, used in the projection GEMMs only)
__device__ __forceinline__ void mma16816h(float* c, const u32* a, const u32* b) {
    asm volatile(
        "mma.sync.aligned.m16n8k16.row.col.f32.f16.f16.f32 "
        "{%0,%1,%2,%3}, {%4,%5,%6,%7}, {%8,%9}, {%0,%1,%2,%3};"
        : "+f"(c[0]), "+f"(c[1]), "+f"(c[2]), "+f"(c[3])
        : "r"(a[0]), "r"(a[1]), "r"(a[2]), "r"(a[3]), "r"(b[0]), "r"(b[1]));
}
__device__ __forceinline__ u32 packhi(float a, float b) {
    return ((u32)__bfloat16_as_ushort(__float2bfloat16(a)))
         | ((u32)__bfloat16_as_ushort(__float2bfloat16(b)) << 16);
}
__device__ __forceinline__ u32 packlo(float a, float b) {
    float al = a - __bfloat162float(__float2bfloat16(a));
    float bl = b - __bfloat162float(__float2bfloat16(b));
    return ((u32)__bfloat16_as_ushort(__float2bfloat16(al)))
         | ((u32)__bfloat16_as_ushort(__float2bfloat16(bl)) << 16);
}
__device__ __forceinline__ u32 packh(float a, float b) {
    __half2 v = __floats2half2_rn(a, b);
    return *(u32*)&v;
}
__device__ __forceinline__ float tanha(float x) {
    float y;
    asm("tanh.approx.f32 %0, %1;" : "=f"(y) : "f"(x));
    return y;
}
__device__ __forceinline__ float siga(float x) {
    return fmaf(0.5f, tanha(0.5f * x), 0.5f);
}

// ================================================================= GEMM
// OUT[m][n] = sum_k X[m][k]·W[n][k] + bias[n].
// SINGLE-TERM fp16 HMMA (fp32 accum): 1/3 the MMA work of the bf16 3-term
// split; gx noise ~5e-4 relative (one-shot, same class as R10's measured
// 2e-4). Layout identical to the R8-proven version minus the lo buffers.
template<int K>
__global__ __launch_bounds__(256, 1)
void proj_gemm(const float* __restrict__ X,
               const float* __restrict__ W,
               const float* __restrict__ bias,
               float* __restrict__ OUT)
{
    constexpr int P      = K + 8;
    constexpr int NTILES = MTOT / 64;
    constexpr int ABUF   = 64 * P * 2;        // one A buffer (fp16)
    constexpr int BBUF   = G3 * P * 2;
    constexpr int NPF    = K / 16;

    extern __shared__ char smem[];
    char* Bh    = smem;
    char* Abase = smem + BBUF;                // [buf(2)]

    const int tid = threadIdx.x;
    const int wid = tid >> 5;
    const int lid = tid & 31;
    const int g   = lid >> 2;
    const int cp  = lid & 3;
    const int GRID = gridDim.x;

    // ---- stage B (fp16) once ----
    for (int c = tid; c < G3 * (K / 8); c += 256) {
        int row = c / (K / 8), k = (c % (K / 8)) * 8;
        const float4* src = (const float4*)(W + row * K + k);
        float4 v0 = src[0], v1 = src[1];
        int byte = (row * P + k) * 2;
        *(uint4*)(Bh + byte) = make_uint4(packh(v0.x, v0.y), packh(v0.z, v0.w),
                                          packh(v1.x, v1.y), packh(v1.z, v1.w));
    }

    const int mrow = (wid & 1) * 32;
    const int ncol = (wid >> 1) * 48;

    float breg[6][2];
#pragma unroll
    for (int nt = 0; nt < 6; nt++) {
        int col = ncol + nt * 8 + 2 * cp;
        breg[nt][0] = bias[col];
        breg[nt][1] = bias[col + 1];
    }

    float4 pfA[NPF];
    long tile0 = blockIdx.x;
    if (tile0 < NTILES) {
#pragma unroll
        for (int q = 0; q < NPF; q++) {
            int idx = tid + 256 * q;
            int row = idx / (K / 4), k = (idx % (K / 4)) * 4;
            pfA[q] = *(const float4*)(X + (tile0 * 64 + row) * K + k);
        }
        char* Ah = Abase;
#pragma unroll
        for (int q = 0; q < NPF; q++) {
            int idx = tid + 256 * q;
            int row = idx / (K / 4), k = (idx % (K / 4)) * 4;
            float4 v = pfA[q];
            *(uint2*)(Ah + (row * P + k) * 2) = make_uint2(packh(v.x, v.y), packh(v.z, v.w));
        }
    }
    __syncthreads();

    int it = 0;
    for (long tile = tile0; tile < NTILES; tile += GRID, it++) {
        const long nxt = tile + GRID;
        if (nxt < NTILES) {
#pragma unroll
            for (int q = 0; q < NPF; q++) {
                int idx = tid + 256 * q;
                int row = idx / (K / 4), k = (idx % (K / 4)) * 4;
                pfA[q] = *(const float4*)(X + (nxt * 64 + row) * K + k);
            }
        }

        char* Ah = Abase + (it & 1) * ABUF;

        float acc[2][6][4];
#pragma unroll
        for (int mt = 0; mt < 2; mt++)
#pragma unroll
            for (int nt = 0; nt < 6; nt++)
#pragma unroll
                for (int q = 0; q < 4; q++) acc[mt][nt][q] = 0.0f;

#pragma unroll
        for (int ks = 0; ks < K / 16; ks++) {
            const int kb = ks * 16;
            u32 ahf[2][4];
#pragma unroll
            for (int mt = 0; mt < 2; mt++) {
                int r = mrow + mt * 16 + g;
                int c0b = (r * P + kb + 2 * cp) * 2;
                int c1b = ((r + 8) * P + kb + 2 * cp) * 2;
                ahf[mt][0] = *(const u32*)(Ah + c0b);
                ahf[mt][1] = *(const u32*)(Ah + c1b);
                ahf[mt][2] = *(const u32*)(Ah + c0b + 16);
                ahf[mt][3] = *(const u32*)(Ah + c1b + 16);
            }
            u32 bhf[6][2];
#pragma unroll
            for (int nt = 0; nt < 6; nt++) {
                int n = ncol + nt * 8 + g;
                int bb = (n * P + kb + 2 * cp) * 2;
                bhf[nt][0] = *(const u32*)(Bh + bb);
                bhf[nt][1] = *(const u32*)(Bh + bb + 16);
            }
#pragma unroll
            for (int mt = 0; mt < 2; mt++)
#pragma unroll
                for (int nt = 0; nt < 6; nt++)
                    mma16816h(acc[mt][nt], ahf[mt], bhf[nt]);
        }

        // stage next tile first, then epilogue STGs drain
        if (nxt < NTILES) {
            char* nAh = Abase + ((it + 1) & 1) * ABUF;
#pragma unroll
            for (int q = 0; q < NPF; q++) {
                int idx = tid + 256 * q;
                int row = idx / (K / 4), k = (idx % (K / 4)) * 4;
                float4 v = pfA[q];
                *(uint2*)(nAh + (row * P + k) * 2) = make_uint2(packh(v.x, v.y), packh(v.z, v.w));
            }
        }

#pragma unroll
        for (int mt = 0; mt < 2; mt++) {
            long r0 = tile * 64 + mrow + mt * 16 + g;
#pragma unroll
            for (int nt = 0; nt < 6; nt++) {
                int col = ncol + nt * 8 + 2 * cp;
                *(float2*)(OUT + r0 * G3 + col) =
                    make_float2(acc[mt][nt][0] + breg[nt][0], acc[mt][nt][1] + breg[nt][1]);
                *(float2*)(OUT + (r0 + 8) * G3 + col) =
                    make_float2(acc[mt][nt][2] + breg[nt][0], acc[mt][nt][3] + breg[nt][1]);
            }
        }
        __syncthreads();
    }
}

// ============================================================ recurrence (HMMA) — R8 verbatim
// 32 rows in TWO independent 16-row groups (warps 0-3 / 4-7), named barriers
// + nanosleep stagger; warp tile m16 x n48; W_hh in B-fragment registers
// (hi/lo bf16, 3-term — full precision preserved on the serial path).
#define BBR 32
#define NTR 256
#define PAB 144
#define PG  196

template<bool FIRST>
__global__ __launch_bounds__(NTR, 1)
void gru_hmma(const float* __restrict__ GX,
              const float* __restrict__ Whh,
              const float* __restrict__ bhh,
              const float* __restrict__ Wfc,
              const float* __restrict__ bfc,
              float* __restrict__ hout,
              float* __restrict__ out)
{
    extern __shared__ char smemc[];
    char*  sAh = smemc;
    char*  sAl = sAh + BBR * PAB;
    float* sGh = (float*)(sAl + BBR * PAB);

    const int tid = threadIdx.x;
    const int wid = tid >> 5;
    const int lid = tid & 31;
    const int g   = lid >> 2;
    const int cp  = lid & 3;
    const int b0  = blockIdx.x * BBR;

    const int grp  = wid >> 2;
    const int mrow = grp * 16;
    const int ncol = (wid & 3) * 48;

    u32 bh[4][6][2], bl[4][6][2];
    float bhv[6][2];
#pragma unroll
    for (int nt = 0; nt < 6; nt++) {
        int n = ncol + nt * 8 + g;
#pragma unroll
        for (int kc = 0; kc < 4; kc++) {
            int k0 = kc * 16 + 2 * cp;
            float w0 = Whh[n * HID + k0],     w1 = Whh[n * HID + k0 + 1];
            float w2 = Whh[n * HID + k0 + 8], w3 = Whh[n * HID + k0 + 9];
            bh[kc][nt][0] = packhi(w0, w1);  bh[kc][nt][1] = packhi(w2, w3);
            bl[kc][nt][0] = packlo(w0, w1);  bl[kc][nt][1] = packlo(w2, w3);
        }
        int colc = ncol + nt * 8 + 2 * cp;
        bhv[nt][0] = bhh[colc];
        bhv[nt][1] = bhh[colc + 1];
    }

    const int gtid = tid & 127;
    const int grow = mrow + (gtid >> 3);
    const int uc   = gtid & 7;
    const long gxrow0 = ((long)(b0 + grow) * SEQT) * G3 + uc * 8;

    float wfc[8];
    if (!FIRST) {
#pragma unroll
        for (int s = 0; s < 8; s++) wfc[s] = Wfc[uc * 8 + s];
    }
    float hreg[8];
#pragma unroll
    for (int s = 0; s < 8; s++) hreg[s] = 0.0f;

    for (int i = tid; i < BBR * PAB / 4; i += NTR) {
        ((u32*)sAh)[i] = 0u;
        ((u32*)sAl)[i] = 0u;
    }
    __syncthreads();

    float4 pf[6];
#pragma unroll
    for (int g3 = 0; g3 < 3; g3++) {
        pf[g3 * 2]     = *(const float4*)(GX + gxrow0 + g3 * 64);
        pf[g3 * 2 + 1] = *(const float4*)(GX + gxrow0 + g3 * 64 + 4);
    }

    if (grp == 1) __nanosleep(400);
    const u32 barid = grp + 1;

    for (int t = 0; t < SEQT; t++) {
        float acc[6][4];
#pragma unroll
        for (int nt = 0; nt < 6; nt++)
#pragma unroll
            for (int q = 0; q < 4; q++) acc[nt][q] = 0.0f;

#pragma unroll
        for (int kc = 0; kc < 4; kc++) {
            const int kb = kc * 16;
            u32 ahf[4], alf[4];
            {
                int r = mrow + g;
                int c0b = r * PAB + (kb + 2 * cp) * 2;
                int c1b = (r + 8) * PAB + (kb + 2 * cp) * 2;
                ahf[0] = *(const u32*)(sAh + c0b);
                ahf[1] = *(const u32*)(sAh + c1b);
                ahf[2] = *(const u32*)(sAh + c0b + 16);
                ahf[3] = *(const u32*)(sAh + c1b + 16);
                alf[0] = *(const u32*)(sAl + c0b);
                alf[1] = *(const u32*)(sAl + c1b);
                alf[2] = *(const u32*)(sAl + c0b + 16);
                alf[3] = *(const u32*)(sAl + c1b + 16);
            }
#pragma unroll
            for (int nt = 0; nt < 6; nt++) {
                mma16816(acc[nt], ahf, bh[kc][nt]);
                mma16816(acc[nt], ahf, bl[kc][nt]);
                mma16816(acc[nt], alf, bh[kc][nt]);
            }
        }
#pragma unroll
        for (int nt = 0; nt < 6; nt++) {
            int col = ncol + nt * 8 + 2 * cp;
            *(float2*)(sGh + (mrow + g) * PG + col) =
                make_float2(acc[nt][0] + bhv[nt][0], acc[nt][1] + bhv[nt][1]);
            *(float2*)(sGh + (mrow + g + 8) * PG + col) =
                make_float2(acc[nt][2] + bhv[nt][0], acc[nt][3] + bhv[nt][1]);
        }
        asm volatile("bar.sync %0, 128;" :: "r"(barid) : "memory");

        {
            const float* gr = sGh + grow * PG + uc * 8;
            float4 r0 = *(const float4*)(gr);
            float4 r1 = *(const float4*)(gr + 4);
            float4 z0 = *(const float4*)(gr + 64);
            float4 z1 = *(const float4*)(gr + 68);
            float4 n0 = *(const float4*)(gr + 128);
            float4 n1 = *(const float4*)(gr + 132);
            float ghr[8] = {r0.x, r0.y, r0.z, r0.w, r1.x, r1.y, r1.z, r1.w};
            float ghz[8] = {z0.x, z0.y, z0.z, z0.w, z1.x, z1.y, z1.z, z1.w};
            float ghn[8] = {n0.x, n0.y, n0.z, n0.w, n1.x, n1.y, n1.z, n1.w};
            float gxr[8] = {pf[0].x, pf[0].y, pf[0].z, pf[0].w, pf[1].x, pf[1].y, pf[1].z, pf[1].w};
            float gxz[8] = {pf[2].x, pf[2].y, pf[2].z, pf[2].w, pf[3].x, pf[3].y, pf[3].z, pf[3].w};
            float gxn[8] = {pf[4].x, pf[4].y, pf[4].z, pf[4].w, pf[5].x, pf[5].y, pf[5].z, pf[5].w};

            float h[8];
#pragma unroll
            for (int s = 0; s < 8; s++) {
                float rg = siga(gxr[s] + ghr[s]);
                float zg = siga(gxz[s] + ghz[s]);
                float ng = tanha(gxn[s] + rg * ghn[s]);
                h[s] = ng + zg * (hreg[s] - ng);
                hreg[s] = h[s];
            }
            int abyte = grow * PAB + uc * 16;
            *(uint4*)(sAh + abyte) = make_uint4(packhi(h[0], h[1]), packhi(h[2], h[3]),
                                                packhi(h[4], h[5]), packhi(h[6], h[7]));
            *(uint4*)(sAl + abyte) = make_uint4(packlo(h[0], h[1]), packlo(h[2], h[3]),
                                                packlo(h[4], h[5]), packlo(h[6], h[7]));
            if (FIRST) {
                float* hp = hout + ((long)(b0 + grow) * SEQT + t) * HID + uc * 8;
                *(float4*)(hp)     = make_float4(h[0], h[1], h[2], h[3]);
                *(float4*)(hp + 4) = make_float4(h[4], h[5], h[6], h[7]);
            }
            if (t + 1 < SEQT) {
                const float* gp = GX + gxrow0 + (long)(t + 1) * G3;
#pragma unroll
                for (int g3 = 0; g3 < 3; g3++) {
                    pf[g3 * 2]     = *(const float4*)(gp + g3 * 64);
                    pf[g3 * 2 + 1] = *(const float4*)(gp + g3 * 64 + 4);
                }
            }
        }
        asm volatile("bar.sync %0, 128;" :: "r"(barid) : "memory");
    }

    if (!FIRST) {
        float s = 0.0f;
#pragma unroll
        for (int q = 0; q < 8; q++) s += hreg[q] * wfc[q];
        s += __shfl_xor_sync(0xFFFFFFFF, s, 1);
        s += __shfl_xor_sync(0xFFFFFFFF, s, 2);
        s += __shfl_xor_sync(0xFFFFFFFF, s, 4);
        if (uc == 0) out[b0 + grow] = s + bfc[0];
    }
}

// ================================================================= host
extern "C" void kernel_launch(void* const* d_in, const int* in_sizes, int n_in,
                              void* d_out, int out_size)
{
    const float* x    = (const float*)d_in[0];
    const float* Wih0 = (const float*)d_in[1];
    const float* Whh0 = (const float*)d_in[2];
    const float* bih0 = (const float*)d_in[3];
    const float* bhh0 = (const float*)d_in[4];
    const float* Wih1 = (const float*)d_in[5];
    const float* Whh1 = (const float*)d_in[6];
    const float* bih1 = (const float*)d_in[7];
    const float* bhh1 = (const float*)d_in[8];
    const float* Wfc  = (const float*)d_in[9];
    const float* bfc  = (const float*)d_in[10];
    float* out = (float*)d_out;

    float *gx, *h1;
    cudaGetSymbolAddress((void**)&gx, g_gx);
    cudaGetSymbolAddress((void**)&h1, g_h1);

    // fp16 single buffers: B + 2x A
    const int smG1 = (G3 * (DIN0 + 8) * 2) + 2 * (64 * (DIN0 + 8) * 2);   // 86,? ~ 87040
    const int smG2 = (G3 * (HID + 8) * 2)  + 2 * (64 * (HID + 8) * 2);    // 46080
    const int smR  = 2 * BBR * PAB + BBR * PG * 4;

    cudaFuncSetAttribute(proj_gemm<DIN0>, cudaFuncAttributeMaxDynamicSharedMemorySize, smG1);
    cudaFuncSetAttribute(proj_gemm<HID>,  cudaFuncAttributeMaxDynamicSharedMemorySize, smG2);
    cudaFuncSetAttribute(gru_hmma<true>,  cudaFuncAttributeMaxDynamicSharedMemorySize, smR);
    cudaFuncSetAttribute(gru_hmma<false>, cudaFuncAttributeMaxDynamicSharedMemorySize, smR);

    proj_gemm<DIN0><<<148, 256, smG1>>>(x, Wih0, bih0, gx);
    gru_hmma<true><<<BATCH / BBR, NTR, smR>>>(gx, Whh0, bhh0, nullptr, nullptr, h1, nullptr);
    proj_gemm<HID><<<296, 256, smG2>>>(h1, Wih1, bih1, gx);
    gru_hmma<false><<<BATCH / BBR, NTR, smR>>>(gx, Whh1, bhh1, Wfc, bfc, nullptr, out);
}

// round 16
// speedup vs baseline: 1.5469x; 1.1087x over previous
#include <cuda_runtime.h>
#include <cuda_bf16.h>
#include <cuda_fp16.h>
#include <stdint.h>

#define BATCH 4096
#define SEQT  256
#define DIN0  128
#define HID   64
#define G3    192
#define MTOT  (BATCH * SEQT)   // 1048576 rows

// Scratch (static: no allocations allowed)
__device__ float g_gx[(long)MTOT * G3];   // fp32 gate preactivations incl b_ih (reused both layers)
__device__ float g_h1[(long)MTOT * HID];  // layer-1 hidden sequence

typedef unsigned long long u64;
typedef unsigned int u32;

// ---------------------------------------------------------------- common
// fp16 single-term MMA (fp32 accum) — both GEMMs and recurrence
__device__ __forceinline__ void mma16816h(float* c, const u32* a, const u32* b) {
    asm volatile(
        "mma.sync.aligned.m16n8k16.row.col.f32.f16.f16.f32 "
        "{%0,%1,%2,%3}, {%4,%5,%6,%7}, {%8,%9}, {%0,%1,%2,%3};"
        : "+f"(c[0]), "+f"(c[1]), "+f"(c[2]), "+f"(c[3])
        : "r"(a[0]), "r"(a[1]), "r"(a[2]), "r"(a[3]), "r"(b[0]), "r"(b[1]));
}
__device__ __forceinline__ u32 packh(float a, float b) {
    __half2 v = __floats2half2_rn(a, b);
    return *(u32*)&v;
}
__device__ __forceinline__ float tanha(float x) {
    float y;
    asm("tanh.approx.f32 %0, %1;" : "=f"(y) : "f"(x));
    return y;
}
__device__ __forceinline__ float siga(float x) {
    return fmaf(0.5f, tanha(0.5f * x), 0.5f);
}

// ================================================================= GEMM
// OUT[m][n] = sum_k X[m][k]·W[n][k] + bias[n]. fp16 single-term (R15-proven).
template<int K>
__global__ __launch_bounds__(256, 1)
void proj_gemm(const float* __restrict__ X,
               const float* __restrict__ W,
               const float* __restrict__ bias,
               float* __restrict__ OUT)
{
    constexpr int P      = K + 8;
    constexpr int NTILES = MTOT / 64;
    constexpr int ABUF   = 64 * P * 2;
    constexpr int BBUF   = G3 * P * 2;
    constexpr int NPF    = K / 16;

    extern __shared__ char smem[];
    char* Bh    = smem;
    char* Abase = smem + BBUF;

    const int tid = threadIdx.x;
    const int wid = tid >> 5;
    const int lid = tid & 31;
    const int g   = lid >> 2;
    const int cp  = lid & 3;
    const int GRID = gridDim.x;

    for (int c = tid; c < G3 * (K / 8); c += 256) {
        int row = c / (K / 8), k = (c % (K / 8)) * 8;
        const float4* src = (const float4*)(W + row * K + k);
        float4 v0 = src[0], v1 = src[1];
        int byte = (row * P + k) * 2;
        *(uint4*)(Bh + byte) = make_uint4(packh(v0.x, v0.y), packh(v0.z, v0.w),
                                          packh(v1.x, v1.y), packh(v1.z, v1.w));
    }

    const int mrow = (wid & 1) * 32;
    const int ncol = (wid >> 1) * 48;

    float breg[6][2];
#pragma unroll
    for (int nt = 0; nt < 6; nt++) {
        int col = ncol + nt * 8 + 2 * cp;
        breg[nt][0] = bias[col];
        breg[nt][1] = bias[col + 1];
    }

    float4 pfA[NPF];
    long tile0 = blockIdx.x;
    if (tile0 < NTILES) {
#pragma unroll
        for (int q = 0; q < NPF; q++) {
            int idx = tid + 256 * q;
            int row = idx / (K / 4), k = (idx % (K / 4)) * 4;
            pfA[q] = *(const float4*)(X + (tile0 * 64 + row) * K + k);
        }
        char* Ah = Abase;
#pragma unroll
        for (int q = 0; q < NPF; q++) {
            int idx = tid + 256 * q;
            int row = idx / (K / 4), k = (idx % (K / 4)) * 4;
            float4 v = pfA[q];
            *(uint2*)(Ah + (row * P + k) * 2) = make_uint2(packh(v.x, v.y), packh(v.z, v.w));
        }
    }
    __syncthreads();

    int it = 0;
    for (long tile = tile0; tile < NTILES; tile += GRID, it++) {
        const long nxt = tile + GRID;
        if (nxt < NTILES) {
#pragma unroll
            for (int q = 0; q < NPF; q++) {
                int idx = tid + 256 * q;
                int row = idx / (K / 4), k = (idx % (K / 4)) * 4;
                pfA[q] = *(const float4*)(X + (nxt * 64 + row) * K + k);
            }
        }

        char* Ah = Abase + (it & 1) * ABUF;

        float acc[2][6][4];
#pragma unroll
        for (int mt = 0; mt < 2; mt++)
#pragma unroll
            for (int nt = 0; nt < 6; nt++)
#pragma unroll
                for (int q = 0; q < 4; q++) acc[mt][nt][q] = 0.0f;

#pragma unroll
        for (int ks = 0; ks < K / 16; ks++) {
            const int kb = ks * 16;
            u32 ahf[2][4];
#pragma unroll
            for (int mt = 0; mt < 2; mt++) {
                int r = mrow + mt * 16 + g;
                int c0b = (r * P + kb + 2 * cp) * 2;
                int c1b = ((r + 8) * P + kb + 2 * cp) * 2;
                ahf[mt][0] = *(const u32*)(Ah + c0b);
                ahf[mt][1] = *(const u32*)(Ah + c1b);
                ahf[mt][2] = *(const u32*)(Ah + c0b + 16);
                ahf[mt][3] = *(const u32*)(Ah + c1b + 16);
            }
            u32 bhf[6][2];
#pragma unroll
            for (int nt = 0; nt < 6; nt++) {
                int n = ncol + nt * 8 + g;
                int bb = (n * P + kb + 2 * cp) * 2;
                bhf[nt][0] = *(const u32*)(Bh + bb);
                bhf[nt][1] = *(const u32*)(Bh + bb + 16);
            }
#pragma unroll
            for (int mt = 0; mt < 2; mt++)
#pragma unroll
                for (int nt = 0; nt < 6; nt++)
                    mma16816h(acc[mt][nt], ahf[mt], bhf[nt]);
        }

        if (nxt < NTILES) {
            char* nAh = Abase + ((it + 1) & 1) * ABUF;
#pragma unroll
            for (int q = 0; q < NPF; q++) {
                int idx = tid + 256 * q;
                int row = idx / (K / 4), k = (idx % (K / 4)) * 4;
                float4 v = pfA[q];
                *(uint2*)(nAh + (row * P + k) * 2) = make_uint2(packh(v.x, v.y), packh(v.z, v.w));
            }
        }

#pragma unroll
        for (int mt = 0; mt < 2; mt++) {
            long r0 = tile * 64 + mrow + mt * 16 + g;
#pragma unroll
            for (int nt = 0; nt < 6; nt++) {
                int col = ncol + nt * 8 + 2 * cp;
                *(float2*)(OUT + r0 * G3 + col) =
                    make_float2(acc[mt][nt][0] + breg[nt][0], acc[mt][nt][1] + breg[nt][1]);
                *(float2*)(OUT + (r0 + 8) * G3 + col) =
                    make_float2(acc[mt][nt][2] + breg[nt][0], acc[mt][nt][3] + breg[nt][1]);
            }
        }
        __syncthreads();
    }
}

// ============================================================ recurrence (HMMA, fp16 single-term)
// R8 structure (32 rows, 2 independent 16-row groups, named barriers, stagger,
// warp tile m16 x n48) but MMA is SINGLE-TERM fp16: 24 HMMA/warp/step (was 72).
// W_hh single fp16 B-fragments in registers; h stored fp16 in one A-tile.
// Error model anchored on R10's measurement (per-step 5e-4 gate noise -> 2e-4
// final): predicted total rel_err ~5-6e-4. Revert if >= 8e-4.
#define BBR 32
#define NTR 256
#define PAB 144
#define PG  196

template<bool FIRST>
__global__ __launch_bounds__(NTR, 1)
void gru_hmma(const float* __restrict__ GX,
              const float* __restrict__ Whh,
              const float* __restrict__ bhh,
              const float* __restrict__ Wfc,
              const float* __restrict__ bfc,
              float* __restrict__ hout,
              float* __restrict__ out)
{
    extern __shared__ char smemc[];
    char*  sAh = smemc;                        // [32][PAB] fp16 h tile
    float* sGh = (float*)(sAh + BBR * PAB);    // [32][PG] fp32 gh (incl b_hh)

    const int tid = threadIdx.x;
    const int wid = tid >> 5;
    const int lid = tid & 31;
    const int g   = lid >> 2;
    const int cp  = lid & 3;
    const int b0  = blockIdx.x * BBR;

    const int grp  = wid >> 2;
    const int mrow = grp * 16;
    const int ncol = (wid & 3) * 48;

    // W_hh fragments (single fp16) + b_hh
    u32 bh[4][6][2];
    float bhv[6][2];
#pragma unroll
    for (int nt = 0; nt < 6; nt++) {
        int n = ncol + nt * 8 + g;
#pragma unroll
        for (int kc = 0; kc < 4; kc++) {
            int k0 = kc * 16 + 2 * cp;
            bh[kc][nt][0] = packh(Whh[n * HID + k0],     Whh[n * HID + k0 + 1]);
            bh[kc][nt][1] = packh(Whh[n * HID + k0 + 8], Whh[n * HID + k0 + 9]);
        }
        int colc = ncol + nt * 8 + 2 * cp;
        bhv[nt][0] = bhh[colc];
        bhv[nt][1] = bhh[colc + 1];
    }

    const int gtid = tid & 127;
    const int grow = mrow + (gtid >> 3);
    const int uc   = gtid & 7;
    const long gxrow0 = ((long)(b0 + grow) * SEQT) * G3 + uc * 8;

    float wfc[8];
    if (!FIRST) {
#pragma unroll
        for (int s = 0; s < 8; s++) wfc[s] = Wfc[uc * 8 + s];
    }
    float hreg[8];
#pragma unroll
    for (int s = 0; s < 8; s++) hreg[s] = 0.0f;

    for (int i = tid; i < BBR * PAB / 4; i += NTR)
        ((u32*)sAh)[i] = 0u;
    __syncthreads();

    float4 pf[6];
#pragma unroll
    for (int g3 = 0; g3 < 3; g3++) {
        pf[g3 * 2]     = *(const float4*)(GX + gxrow0 + g3 * 64);
        pf[g3 * 2 + 1] = *(const float4*)(GX + gxrow0 + g3 * 64 + 4);
    }

    if (grp == 1) __nanosleep(400);
    const u32 barid = grp + 1;

    for (int t = 0; t < SEQT; t++) {
        // ---------- MMA phase: gh = Whh·h (24 HMMA) ----------
        float acc[6][4];
#pragma unroll
        for (int nt = 0; nt < 6; nt++)
#pragma unroll
            for (int q = 0; q < 4; q++) acc[nt][q] = 0.0f;

#pragma unroll
        for (int kc = 0; kc < 4; kc++) {
            const int kb = kc * 16;
            u32 ahf[4];
            {
                int r = mrow + g;
                int c0b = r * PAB + (kb + 2 * cp) * 2;
                int c1b = (r + 8) * PAB + (kb + 2 * cp) * 2;
                ahf[0] = *(const u32*)(sAh + c0b);
                ahf[1] = *(const u32*)(sAh + c1b);
                ahf[2] = *(const u32*)(sAh + c0b + 16);
                ahf[3] = *(const u32*)(sAh + c1b + 16);
            }
#pragma unroll
            for (int nt = 0; nt < 6; nt++)
                mma16816h(acc[nt], ahf, bh[kc][nt]);
        }
#pragma unroll
        for (int nt = 0; nt < 6; nt++) {
            int col = ncol + nt * 8 + 2 * cp;
            *(float2*)(sGh + (mrow + g) * PG + col) =
                make_float2(acc[nt][0] + bhv[nt][0], acc[nt][1] + bhv[nt][1]);
            *(float2*)(sGh + (mrow + g + 8) * PG + col) =
                make_float2(acc[nt][2] + bhv[nt][0], acc[nt][3] + bhv[nt][1]);
        }
        asm volatile("bar.sync %0, 128;" :: "r"(barid) : "memory");

        // ---------- gate phase ----------
        {
            const float* gr = sGh + grow * PG + uc * 8;
            float4 r0 = *(const float4*)(gr);
            float4 r1 = *(const float4*)(gr + 4);
            float4 z0 = *(const float4*)(gr + 64);
            float4 z1 = *(const float4*)(gr + 68);
            float4 n0 = *(const float4*)(gr + 128);
            float4 n1 = *(const float4*)(gr + 132);
            float ghr[8] = {r0.x, r0.y, r0.z, r0.w, r1.x, r1.y, r1.z, r1.w};
            float ghz[8] = {z0.x, z0.y, z0.z, z0.w, z1.x, z1.y, z1.z, z1.w};
            float ghn[8] = {n0.x, n0.y, n0.z, n0.w, n1.x, n1.y, n1.z, n1.w};
            float gxr[8] = {pf[0].x, pf[0].y, pf[0].z, pf[0].w, pf[1].x, pf[1].y, pf[1].z, pf[1].w};
            float gxz[8] = {pf[2].x, pf[2].y, pf[2].z, pf[2].w, pf[3].x, pf[3].y, pf[3].z, pf[3].w};
            float gxn[8] = {pf[4].x, pf[4].y, pf[4].z, pf[4].w, pf[5].x, pf[5].y, pf[5].z, pf[5].w};

            float h[8];
#pragma unroll
            for (int s = 0; s < 8; s++) {
                float rg = siga(gxr[s] + ghr[s]);
                float zg = siga(gxz[s] + ghz[s]);
                float ng = tanha(gxn[s] + rg * ghn[s]);
                h[s] = ng + zg * (hreg[s] - ng);
                hreg[s] = h[s];
            }
            int abyte = grow * PAB + uc * 16;
            *(uint4*)(sAh + abyte) = make_uint4(packh(h[0], h[1]), packh(h[2], h[3]),
                                                packh(h[4], h[5]), packh(h[6], h[7]));
            if (FIRST) {
                float* hp = hout + ((long)(b0 + grow) * SEQT + t) * HID + uc * 8;
                *(float4*)(hp)     = make_float4(h[0], h[1], h[2], h[3]);
                *(float4*)(hp + 4) = make_float4(h[4], h[5], h[6], h[7]);
            }
            if (t + 1 < SEQT) {
                const float* gp = GX + gxrow0 + (long)(t + 1) * G3;
#pragma unroll
                for (int g3 = 0; g3 < 3; g3++) {
                    pf[g3 * 2]     = *(const float4*)(gp + g3 * 64);
                    pf[g3 * 2 + 1] = *(const float4*)(gp + g3 * 64 + 4);
                }
            }
        }
        asm volatile("bar.sync %0, 128;" :: "r"(barid) : "memory");
    }

    if (!FIRST) {
        float s = 0.0f;
#pragma unroll
        for (int q = 0; q < 8; q++) s += hreg[q] * wfc[q];
        s += __shfl_xor_sync(0xFFFFFFFF, s, 1);
        s += __shfl_xor_sync(0xFFFFFFFF, s, 2);
        s += __shfl_xor_sync(0xFFFFFFFF, s, 4);
        if (uc == 0) out[b0 + grow] = s + bfc[0];
    }
}

// ================================================================= host
extern "C" void kernel_launch(void* const* d_in, const int* in_sizes, int n_in,
                              void* d_out, int out_size)
{
    const float* x    = (const float*)d_in[0];
    const float* Wih0 = (const float*)d_in[1];
    const float* Whh0 = (const float*)d_in[2];
    const float* bih0 = (const float*)d_in[3];
    const float* bhh0 = (const float*)d_in[4];
    const float* Wih1 = (const float*)d_in[5];
    const float* Whh1 = (const float*)d_in[6];
    const float* bih1 = (const float*)d_in[7];
    const float* bhh1 = (const float*)d_in[8];
    const float* Wfc  = (const float*)d_in[9];
    const float* bfc  = (const float*)d_in[10];
    float* out = (float*)d_out;

    float *gx, *h1;
    cudaGetSymbolAddress((void**)&gx, g_gx);
    cudaGetSymbolAddress((void**)&h1, g_h1);

    const int smG1 = (G3 * (DIN0 + 8) * 2) + 2 * (64 * (DIN0 + 8) * 2);
    const int smG2 = (G3 * (HID + 8) * 2)  + 2 * (64 * (HID + 8) * 2);
    const int smR  = BBR * PAB + BBR * PG * 4;   // single fp16 A tile + gh

    cudaFuncSetAttribute(proj_gemm<DIN0>, cudaFuncAttributeMaxDynamicSharedMemorySize, smG1);
    cudaFuncSetAttribute(proj_gemm<HID>,  cudaFuncAttributeMaxDynamicSharedMemorySize, smG2);
    cudaFuncSetAttribute(gru_hmma<true>,  cudaFuncAttributeMaxDynamicSharedMemorySize, smR);
    cudaFuncSetAttribute(gru_hmma<false>, cudaFuncAttributeMaxDynamicSharedMemorySize, smR);

    proj_gemm<DIN0><<<148, 256, smG1>>>(x, Wih0, bih0, gx);
    gru_hmma<true><<<BATCH / BBR, NTR, smR>>>(gx, Whh0, bhh0, nullptr, nullptr, h1, nullptr);
    proj_gemm<HID><<<296, 256, smG2>>>(h1, Wih1, bih1, gx);
    gru_hmma<false><<<BATCH / BBR, NTR, smR>>>(gx, Whh1, bhh1, Wfc, bfc, nullptr, out);
}

// round 17
// speedup vs baseline: 1.9035x; 1.2305x over previous
#include <cuda_runtime.h>
#include <cuda_fp16.h>
#include <stdint.h>

#define BATCH 4096
#define SEQT  256
#define DIN0  128
#define HID   64
#define G3    192
#define MTOT  (BATCH * SEQT)   // 1048576 rows

// Scratch (static: no allocations allowed)
__device__ __half g_gx[(long)MTOT * G3];   // fp16 gate preactivations incl b_ih (reused both layers)
__device__ __half g_h1[(long)MTOT * HID];  // fp16 layer-1 hidden sequence (same quantization the
                                           // recurrence/GEMM2 already apply -> zero extra error)

typedef unsigned long long u64;
typedef unsigned int u32;

// ---------------------------------------------------------------- common
__device__ __forceinline__ void mma16816h(float* c, const u32* a, const u32* b) {
    asm volatile(
        "mma.sync.aligned.m16n8k16.row.col.f32.f16.f16.f32 "
        "{%0,%1,%2,%3}, {%4,%5,%6,%7}, {%8,%9}, {%0,%1,%2,%3};"
        : "+f"(c[0]), "+f"(c[1]), "+f"(c[2]), "+f"(c[3])
        : "r"(a[0]), "r"(a[1]), "r"(a[2]), "r"(a[3]), "r"(b[0]), "r"(b[1]));
}
__device__ __forceinline__ u32 packh(float a, float b) {
    __half2 v = __floats2half2_rn(a, b);
    return *(u32*)&v;
}
__device__ __forceinline__ float tanha(float x) {
    float y;
    asm("tanh.approx.f32 %0, %1;" : "=f"(y) : "f"(x));
    return y;
}
__device__ __forceinline__ float siga(float x) {
    return fmaf(0.5f, tanha(0.5f * x), 0.5f);
}

// ================================================================= GEMM
// OUT[m][n] = fp16( sum_k X[m][k]·W[n][k] + bias[n] ). fp16 single-term HMMA.
// XH: X is fp16 (h1) -> A staging is a pure 16B copy. Else X fp32 (x input).
template<int K, bool XH>
__global__ __launch_bounds__(256, 1)
void proj_gemm(const void* __restrict__ Xv,
               const float* __restrict__ W,
               const float* __restrict__ bias,
               __half* __restrict__ OUT)
{
    constexpr int P      = K + 8;
    constexpr int NTILES = MTOT / 64;
    constexpr int ABUF   = 64 * P * 2;
    constexpr int BBUF   = G3 * P * 2;
    constexpr int NPF    = K / 16;            // fp32 path: float4 per thread
    constexpr int NPH    = K / 32;            // fp16 path: uint4 (8 halves) per thread

    extern __shared__ char smem[];
    char* Bh    = smem;
    char* Abase = smem + BBUF;

    const int tid = threadIdx.x;
    const int wid = tid >> 5;
    const int lid = tid & 31;
    const int g   = lid >> 2;
    const int cp  = lid & 3;
    const int GRID = gridDim.x;

    const float*  Xf = (const float*)Xv;
    const __half* Xh = (const __half*)Xv;

    // ---- stage B (fp16) once ----
    for (int c = tid; c < G3 * (K / 8); c += 256) {
        int row = c / (K / 8), k = (c % (K / 8)) * 8;
        const float4* src = (const float4*)(W + row * K + k);
        float4 v0 = src[0], v1 = src[1];
        int byte = (row * P + k) * 2;
        *(uint4*)(Bh + byte) = make_uint4(packh(v0.x, v0.y), packh(v0.z, v0.w),
                                          packh(v1.x, v1.y), packh(v1.z, v1.w));
    }

    const int mrow = (wid & 1) * 32;
    const int ncol = (wid >> 1) * 48;

    float breg[6][2];
#pragma unroll
    for (int nt = 0; nt < 6; nt++) {
        int col = ncol + nt * 8 + 2 * cp;
        breg[nt][0] = bias[col];
        breg[nt][1] = bias[col + 1];
    }

    float4 pfA[XH ? 1 : NPF];
    uint4  pfH[XH ? NPH : 1];

    auto loadA = [&](long tile) {
        if (XH) {
#pragma unroll
            for (int q = 0; q < NPH; q++) {
                int idx = tid + 256 * q;
                int row = idx / (K / 8), k = (idx % (K / 8)) * 8;
                pfH[q] = *(const uint4*)(Xh + (tile * 64 + row) * K + k);
            }
        } else {
#pragma unroll
            for (int q = 0; q < NPF; q++) {
                int idx = tid + 256 * q;
                int row = idx / (K / 4), k = (idx % (K / 4)) * 4;
                pfA[q] = *(const float4*)(Xf + (tile * 64 + row) * K + k);
            }
        }
    };
    auto stageA = [&](char* Ah) {
        if (XH) {
#pragma unroll
            for (int q = 0; q < NPH; q++) {
                int idx = tid + 256 * q;
                int row = idx / (K / 8), k = (idx % (K / 8)) * 8;
                *(uint4*)(Ah + (row * P + k) * 2) = pfH[q];
            }
        } else {
#pragma unroll
            for (int q = 0; q < NPF; q++) {
                int idx = tid + 256 * q;
                int row = idx / (K / 4), k = (idx % (K / 4)) * 4;
                float4 v = pfA[q];
                *(uint2*)(Ah + (row * P + k) * 2) = make_uint2(packh(v.x, v.y), packh(v.z, v.w));
            }
        }
    };

    long tile0 = blockIdx.x;
    if (tile0 < NTILES) {
        loadA(tile0);
        stageA(Abase);
    }
    __syncthreads();

    int it = 0;
    for (long tile = tile0; tile < NTILES; tile += GRID, it++) {
        const long nxt = tile + GRID;
        if (nxt < NTILES) loadA(nxt);

        char* Ah = Abase + (it & 1) * ABUF;

        float acc[2][6][4];
#pragma unroll
        for (int mt = 0; mt < 2; mt++)
#pragma unroll
            for (int nt = 0; nt < 6; nt++)
#pragma unroll
                for (int q = 0; q < 4; q++) acc[mt][nt][q] = 0.0f;

#pragma unroll
        for (int ks = 0; ks < K / 16; ks++) {
            const int kb = ks * 16;
            u32 ahf[2][4];
#pragma unroll
            for (int mt = 0; mt < 2; mt++) {
                int r = mrow + mt * 16 + g;
                int c0b = (r * P + kb + 2 * cp) * 2;
                int c1b = ((r + 8) * P + kb + 2 * cp) * 2;
                ahf[mt][0] = *(const u32*)(Ah + c0b);
                ahf[mt][1] = *(const u32*)(Ah + c1b);
                ahf[mt][2] = *(const u32*)(Ah + c0b + 16);
                ahf[mt][3] = *(const u32*)(Ah + c1b + 16);
            }
            u32 bhf[6][2];
#pragma unroll
            for (int nt = 0; nt < 6; nt++) {
                int n = ncol + nt * 8 + g;
                int bb = (n * P + kb + 2 * cp) * 2;
                bhf[nt][0] = *(const u32*)(Bh + bb);
                bhf[nt][1] = *(const u32*)(Bh + bb + 16);
            }
#pragma unroll
            for (int mt = 0; mt < 2; mt++)
#pragma unroll
                for (int nt = 0; nt < 6; nt++)
                    mma16816h(acc[mt][nt], ahf[mt], bhf[nt]);
        }

        if (nxt < NTILES) stageA(Abase + ((it + 1) & 1) * ABUF);

        // ---- epilogue: fp16 output ----
#pragma unroll
        for (int mt = 0; mt < 2; mt++) {
            long r0 = tile * 64 + mrow + mt * 16 + g;
#pragma unroll
            for (int nt = 0; nt < 6; nt++) {
                int col = ncol + nt * 8 + 2 * cp;
                *(__half2*)(OUT + r0 * G3 + col) =
                    __floats2half2_rn(acc[mt][nt][0] + breg[nt][0], acc[mt][nt][1] + breg[nt][1]);
                *(__half2*)(OUT + (r0 + 8) * G3 + col) =
                    __floats2half2_rn(acc[mt][nt][2] + breg[nt][0], acc[mt][nt][3] + breg[nt][1]);
            }
        }
        __syncthreads();
    }
}

// ============================================================ recurrence (fp16 single-term)
// R16 structure (32 rows, 2 independent 16-row groups, named barriers,
// stagger, m16 x n48, W_hh fp16 fragments in regs, fp16 h A-tile).
// gx read as fp16 (uint4 of 8 halves, R10-proven); h1 written as fp16.
#define BBR 32
#define NTR 256
#define PAB 144
#define PG  196

template<bool FIRST>
__global__ __launch_bounds__(NTR, 1)
void gru_hmma(const __half* __restrict__ GX,
              const float* __restrict__ Whh,
              const float* __restrict__ bhh,
              const float* __restrict__ Wfc,
              const float* __restrict__ bfc,
              __half* __restrict__ hout,
              float* __restrict__ out)
{
    extern __shared__ char smemc[];
    char*  sAh = smemc;                        // [32][PAB] fp16 h tile
    float* sGh = (float*)(sAh + BBR * PAB);    // [32][PG] fp32 gh (incl b_hh)

    const int tid = threadIdx.x;
    const int wid = tid >> 5;
    const int lid = tid & 31;
    const int g   = lid >> 2;
    const int cp  = lid & 3;
    const int b0  = blockIdx.x * BBR;

    const int grp  = wid >> 2;
    const int mrow = grp * 16;
    const int ncol = (wid & 3) * 48;

    u32 bh[4][6][2];
    float bhv[6][2];
#pragma unroll
    for (int nt = 0; nt < 6; nt++) {
        int n = ncol + nt * 8 + g;
#pragma unroll
        for (int kc = 0; kc < 4; kc++) {
            int k0 = kc * 16 + 2 * cp;
            bh[kc][nt][0] = packh(Whh[n * HID + k0],     Whh[n * HID + k0 + 1]);
            bh[kc][nt][1] = packh(Whh[n * HID + k0 + 8], Whh[n * HID + k0 + 9]);
        }
        int colc = ncol + nt * 8 + 2 * cp;
        bhv[nt][0] = bhh[colc];
        bhv[nt][1] = bhh[colc + 1];
    }

    const int gtid = tid & 127;
    const int grow = mrow + (gtid >> 3);
    const int uc   = gtid & 7;
    const long gxrow0 = ((long)(b0 + grow) * SEQT) * G3 + uc * 8;

    float wfc[8];
    if (!FIRST) {
#pragma unroll
        for (int s = 0; s < 8; s++) wfc[s] = Wfc[uc * 8 + s];
    }
    float hreg[8];
#pragma unroll
    for (int s = 0; s < 8; s++) hreg[s] = 0.0f;

    for (int i = tid; i < BBR * PAB / 4; i += NTR)
        ((u32*)sAh)[i] = 0u;
    __syncthreads();

    // prefetch gx(t=0): 3 gates x 8 fp16 units = 3 x uint4 (16B aligned)
    uint4 pfh[3];
    {
        const __half* gp = GX + gxrow0;
        pfh[0] = *(const uint4*)(gp);
        pfh[1] = *(const uint4*)(gp + 64);
        pfh[2] = *(const uint4*)(gp + 128);
    }

    if (grp == 1) __nanosleep(400);
    const u32 barid = grp + 1;

    for (int t = 0; t < SEQT; t++) {
        // ---------- MMA phase: gh = Whh·h (24 HMMA) ----------
        float acc[6][4];
#pragma unroll
        for (int nt = 0; nt < 6; nt++)
#pragma unroll
            for (int q = 0; q < 4; q++) acc[nt][q] = 0.0f;

#pragma unroll
        for (int kc = 0; kc < 4; kc++) {
            const int kb = kc * 16;
            u32 ahf[4];
            {
                int r = mrow + g;
                int c0b = r * PAB + (kb + 2 * cp) * 2;
                int c1b = (r + 8) * PAB + (kb + 2 * cp) * 2;
                ahf[0] = *(const u32*)(sAh + c0b);
                ahf[1] = *(const u32*)(sAh + c1b);
                ahf[2] = *(const u32*)(sAh + c0b + 16);
                ahf[3] = *(const u32*)(sAh + c1b + 16);
            }
#pragma unroll
            for (int nt = 0; nt < 6; nt++)
                mma16816h(acc[nt], ahf, bh[kc][nt]);
        }
#pragma unroll
        for (int nt = 0; nt < 6; nt++) {
            int col = ncol + nt * 8 + 2 * cp;
            *(float2*)(sGh + (mrow + g) * PG + col) =
                make_float2(acc[nt][0] + bhv[nt][0], acc[nt][1] + bhv[nt][1]);
            *(float2*)(sGh + (mrow + g + 8) * PG + col) =
                make_float2(acc[nt][2] + bhv[nt][0], acc[nt][3] + bhv[nt][1]);
        }
        asm volatile("bar.sync %0, 128;" :: "r"(barid) : "memory");

        // ---------- gate phase ----------
        {
            const float* gr = sGh + grow * PG + uc * 8;
            float4 r0 = *(const float4*)(gr);
            float4 r1 = *(const float4*)(gr + 4);
            float4 z0 = *(const float4*)(gr + 64);
            float4 z1 = *(const float4*)(gr + 68);
            float4 n0 = *(const float4*)(gr + 128);
            float4 n1 = *(const float4*)(gr + 132);
            float ghr[8] = {r0.x, r0.y, r0.z, r0.w, r1.x, r1.y, r1.z, r1.w};
            float ghz[8] = {z0.x, z0.y, z0.z, z0.w, z1.x, z1.y, z1.z, z1.w};
            float ghn[8] = {n0.x, n0.y, n0.z, n0.w, n1.x, n1.y, n1.z, n1.w};

            float gxr[8], gxz[8], gxn[8];
            {
                const __half2* hr = (const __half2*)&pfh[0];
                const __half2* hz = (const __half2*)&pfh[1];
                const __half2* hn = (const __half2*)&pfh[2];
#pragma unroll
                for (int i = 0; i < 4; i++) {
                    float2 fr = __half22float2(hr[i]);
                    float2 fz = __half22float2(hz[i]);
                    float2 fn = __half22float2(hn[i]);
                    gxr[2 * i] = fr.x; gxr[2 * i + 1] = fr.y;
                    gxz[2 * i] = fz.x; gxz[2 * i + 1] = fz.y;
                    gxn[2 * i] = fn.x; gxn[2 * i + 1] = fn.y;
                }
            }

            float h[8];
#pragma unroll
            for (int s = 0; s < 8; s++) {
                float rg = siga(gxr[s] + ghr[s]);
                float zg = siga(gxz[s] + ghz[s]);
                float ng = tanha(gxn[s] + rg * ghn[s]);
                h[s] = ng + zg * (hreg[s] - ng);
                hreg[s] = h[s];
            }
            uint4 hp4 = make_uint4(packh(h[0], h[1]), packh(h[2], h[3]),
                                   packh(h[4], h[5]), packh(h[6], h[7]));
            *(uint4*)(sAh + grow * PAB + uc * 16) = hp4;
            if (FIRST) {
                // fp16 h1 out: identical quantization to the A-tile -> no extra error
                *(uint4*)(hout + ((long)(b0 + grow) * SEQT + t) * HID + uc * 8) = hp4;
            }
            if (t + 1 < SEQT) {
                const __half* gp = GX + gxrow0 + (long)(t + 1) * G3;
                pfh[0] = *(const uint4*)(gp);
                pfh[1] = *(const uint4*)(gp + 64);
                pfh[2] = *(const uint4*)(gp + 128);
            }
        }
        asm volatile("bar.sync %0, 128;" :: "r"(barid) : "memory");
    }

    if (!FIRST) {
        float s = 0.0f;
#pragma unroll
        for (int q = 0; q < 8; q++) s += hreg[q] * wfc[q];
        s += __shfl_xor_sync(0xFFFFFFFF, s, 1);
        s += __shfl_xor_sync(0xFFFFFFFF, s, 2);
        s += __shfl_xor_sync(0xFFFFFFFF, s, 4);
        if (uc == 0) out[b0 + grow] = s + bfc[0];
    }
}

// ================================================================= host
extern "C" void kernel_launch(void* const* d_in, const int* in_sizes, int n_in,
                              void* d_out, int out_size)
{
    const float* x    = (const float*)d_in[0];
    const float* Wih0 = (const float*)d_in[1];
    const float* Whh0 = (const float*)d_in[2];
    const float* bih0 = (const float*)d_in[3];
    const float* bhh0 = (const float*)d_in[4];
    const float* Wih1 = (const float*)d_in[5];
    const float* Whh1 = (const float*)d_in[6];
    const float* bih1 = (const float*)d_in[7];
    const float* bhh1 = (const float*)d_in[8];
    const float* Wfc  = (const float*)d_in[9];
    const float* bfc  = (const float*)d_in[10];
    float* out = (float*)d_out;

    __half *gx, *h1;
    cudaGetSymbolAddress((void**)&gx, g_gx);
    cudaGetSymbolAddress((void**)&h1, g_h1);

    const int smG1 = (G3 * (DIN0 + 8) * 2) + 2 * (64 * (DIN0 + 8) * 2);
    const int smG2 = (G3 * (HID + 8) * 2)  + 2 * (64 * (HID + 8) * 2);
    const int smR  = BBR * PAB + BBR * PG * 4;

    cudaFuncSetAttribute((proj_gemm<DIN0, false>), cudaFuncAttributeMaxDynamicSharedMemorySize, smG1);
    cudaFuncSetAttribute((proj_gemm<HID, true>),   cudaFuncAttributeMaxDynamicSharedMemorySize, smG2);
    cudaFuncSetAttribute(gru_hmma<true>,  cudaFuncAttributeMaxDynamicSharedMemorySize, smR);
    cudaFuncSetAttribute(gru_hmma<false>, cudaFuncAttributeMaxDynamicSharedMemorySize, smR);

    proj_gemm<DIN0, false><<<148, 256, smG1>>>(x, Wih0, bih0, gx);
    gru_hmma<true><<<BATCH / BBR, NTR, smR>>>(gx, Whh0, bhh0, nullptr, nullptr, h1, nullptr);
    proj_gemm<HID, true><<<296, 256, smG2>>>(h1, Wih1, bih1, gx);
    gru_hmma<false><<<BATCH / BBR, NTR, smR>>>(gx, Whh1, bhh1, Wfc, bfc, nullptr, out);
}